// round 14
// baseline (speedup 1.0000x reference)
#include <cuda_runtime.h>
#include <cuda_bf16.h>
#include <math.h>

#define SPX   1024
#define HWPX  16384
#define IMW   128
#define NSTG  6

#define EF_BIAS   1
#define EF_RELU   2
#define EF_GELU   4
#define EF_RES    8
#define EF_F16OUT 16
#define EF_AUX    32

typedef __nv_bfloat16 bf16;

// ---------------------------------------------------------------------------
// Scratch
// ---------------------------------------------------------------------------
__device__ bf16  g_convb[4ull * 16384 * 256];    // NHWC activations [slab*2+br]
__device__ bf16  g_tb[2ull * 16384 * 224];       // NHWC bf16 copies of T1/T2
__device__ bf16  g_wb0[2ull * 9 * 256 * 224];    // stage-0 conv weights
__device__ bf16  g_wbN[10ull * 9 * 256 * 256];   // stage-1..5 conv weights
__device__ bf16  g_wenc[11000832];               // transposed encoder/fc weights
__device__ bf16  g_catb[2ull * 1024 * 512];
__device__ bf16  g_hb[2ull * 1024 * 256];
__device__ bf16  g_qkvb[2ull * 1024 * 1536];
__device__ bf16  g_vT[2ull * 512 * 1024];
__device__ bf16  g_attnob[2ull * 1024 * 512];
__device__ bf16  g_ff1b[2ull * 1024 * 512];
__device__ float g_x[2ull * 1024 * 256];
__device__ float g_dd[1024 * 256];
__device__ float g_hd[1024 * 128];
__device__ int   g_splist[1024 * 64];
__device__ int   g_spcnt[1024];

#define OFF_QKV 0
#define OFF_O   4718592
#define OFF_W1  6291456
#define OFF_W2  7864320
#define OFF_FC0 9437184
#define OFF_FC  9682944

// ---------------------------------------------------------------------------
// cp.async helpers
// ---------------------------------------------------------------------------
#define CPA16(dst, src) \
    asm volatile("cp.async.cg.shared.global [%0], [%1], 16;\n" ::"r"(dst), "l"(src))
#define CPA_COMMIT asm volatile("cp.async.commit_group;\n")
#define CPA_WAIT0  asm volatile("cp.async.wait_group 0;\n")
#define CPA_WAIT1  asm volatile("cp.async.wait_group 1;\n")

// ---------------------------------------------------------------------------
// Block reductions
// ---------------------------------------------------------------------------
__device__ __forceinline__ float blockReduceSum(float v) {
    __shared__ float sh[8];
    int lane = threadIdx.x & 31, w = threadIdx.x >> 5;
#pragma unroll
    for (int o = 16; o; o >>= 1) v += __shfl_xor_sync(0xffffffffu, v, o);
    if (lane == 0) sh[w] = v;
    __syncthreads();
    float r = (threadIdx.x < 8) ? sh[threadIdx.x] : 0.f;
    if (w == 0) {
#pragma unroll
        for (int o = 4; o; o >>= 1) r += __shfl_xor_sync(0xffffffffu, r, o);
        if (lane == 0) sh[0] = r;
    }
    __syncthreads();
    float out = sh[0];
    __syncthreads();
    return out;
}

// ---------------------------------------------------------------------------
// Superpixel list builder
// ---------------------------------------------------------------------------
__global__ void build_sp(const float* __restrict__ Q) {
    int s = blockIdx.x;
    __shared__ int wcnt[8];
    __shared__ int cnt;
    if (threadIdx.x == 0) cnt = 0;
    __syncthreads();
    int lane = threadIdx.x & 31, warp = threadIdx.x >> 5;
    for (int base = 0; base < HWPX; base += 256) {
        int p = base + threadIdx.x;
        bool m = Q[(size_t)p * SPX + s] > 0.5f;
        unsigned bal = __ballot_sync(0xffffffffu, m);
        if (lane == 0) wcnt[warp] = __popc(bal);
        __syncthreads();
        int off = cnt;
        for (int w = 0; w < warp; w++) off += wcnt[w];
        off += __popc(bal & ((1u << lane) - 1u));
        if (m && off < 64) g_splist[s * 64 + off] = p;
        __syncthreads();
        if (threadIdx.x == 0) {
            int t = 0;
            for (int w = 0; w < 8; w++) t += wcnt[w];
            cnt += t;
        }
        __syncthreads();
    }
    if (threadIdx.x == 0) g_spcnt[s] = cnt < 64 ? cnt : 64;
}

// ---------------------------------------------------------------------------
// ct pooling (MLP-16 fast path; identical ascending add order)
// ---------------------------------------------------------------------------
__global__ void ct_nhwc(const bf16* __restrict__ img, long long imgz,
                        bf16* __restrict__ out, long long outz) {
    int s = blockIdx.x, c = threadIdx.x;
    img += (size_t)blockIdx.y * imgz;
    out += (size_t)blockIdx.y * outz;
    int cnt = g_spcnt[s];
    const int* lst = &g_splist[s * 64];
    float sum = 0.f;
    if (cnt == 16) {
        int idxs[16];
#pragma unroll
        for (int i = 0; i < 16; i++) idxs[i] = lst[i];
        float v[16];
#pragma unroll
        for (int i = 0; i < 16; i++)
            v[i] = __bfloat162float(img[(size_t)idxs[i] * 256 + c]);
#pragma unroll
        for (int i = 0; i < 16; i++) sum += v[i];
    } else {
        for (int i = 0; i < cnt; i++)
            sum += __bfloat162float(img[(size_t)lst[i] * 256 + c]);
    }
    out[(size_t)s * 512 + c] = __float2bfloat16(fmaxf(sum / (float)cnt, 0.f));
}

__global__ void ct_mean_f32(const float* __restrict__ img, bf16* __restrict__ out,
                            int coloff) {
    int c = blockIdx.x;
    int s = blockIdx.y * 256 + threadIdx.x;
    int cnt = g_spcnt[s];
    const int* lst = &g_splist[s * 64];
    float sum = 0.f;
    for (int i = 0; i < cnt; i++) sum += img[(size_t)c * HWPX + lst[i]];
    out[(size_t)s * 512 + coloff + c] = __float2bfloat16(fmaxf(sum / (float)cnt, 0.f));
}

// NCHW fp32 -> NHWC bf16 transpose. grid (512, 7), block (32,8).
__global__ void chw2hwc(const float* __restrict__ in, bf16* __restrict__ out, int C) {
    __shared__ float sm[32][33];
    int p0 = blockIdx.x * 32, c0 = blockIdx.y * 32;
    int tx = threadIdx.x, ty = threadIdx.y;
#pragma unroll
    for (int j = 0; j < 4; j++)
        sm[ty + 8 * j][tx] = in[(size_t)(c0 + ty + 8 * j) * HWPX + p0 + tx];
    __syncthreads();
#pragma unroll
    for (int j = 0; j < 4; j++)
        out[(size_t)(p0 + ty + 8 * j) * C + c0 + tx] = __float2bfloat16(sm[tx][ty + 8 * j]);
}

// conv weight repack: [z][oc][ic][3][3] f32 -> [z][tap][oc][ic] bf16
template <int CIN>
__global__ void repack_w(const float* __restrict__ W, bf16* __restrict__ out) {
    int idx = blockIdx.x * 256 + threadIdx.x;
    int t = idx / (256 * CIN);
    int z = t / 9, tap = t % 9;
    int rem = idx - t * 256 * CIN;
    int oc = rem / CIN;
    int ic = rem - oc * CIN;
    out[idx] = __float2bfloat16(W[(size_t)z * 9 * 256 * CIN + ((size_t)oc * CIN + ic) * 9 + tap]);
}

// batched transpose+convert: in [Z][K][N] f32 -> out [Z][N][K] bf16
__global__ void wconv_t(const float* __restrict__ in, bf16* __restrict__ out,
                        int K, int N) {
    __shared__ float sm[32][33];
    int n0 = blockIdx.x * 32, k0 = blockIdx.y * 32;
    const float* inz = in + (size_t)blockIdx.z * K * N;
    bf16* outz = out + (size_t)blockIdx.z * K * N;
    int tx = threadIdx.x, ty = threadIdx.y;
#pragma unroll
    for (int j = 0; j < 4; j++)
        sm[ty + 8 * j][tx] = inz[(size_t)(k0 + ty + 8 * j) * N + n0 + tx];
    __syncthreads();
#pragma unroll
    for (int j = 0; j < 4; j++)
        outz[(size_t)(n0 + ty + 8 * j) * K + k0 + tx] = __float2bfloat16(sm[tx][ty + 8 * j]);
}

// ---------------------------------------------------------------------------
// mma helpers
// ---------------------------------------------------------------------------
__device__ __forceinline__ void mma16816(float* c, const unsigned* a, const unsigned* b) {
    asm volatile(
        "mma.sync.aligned.m16n8k16.row.col.f32.bf16.bf16.f32 "
        "{%0,%1,%2,%3}, {%4,%5,%6,%7}, {%8,%9}, {%0,%1,%2,%3};\n"
        : "+f"(c[0]), "+f"(c[1]), "+f"(c[2]), "+f"(c[3])
        : "r"(a[0]), "r"(a[1]), "r"(a[2]), "r"(a[3]), "r"(b[0]), "r"(b[1]));
}

__device__ __forceinline__ unsigned packbf(float a, float b) {
    __nv_bfloat162 t = __floats2bfloat162_rn(a, b);
    return *(unsigned*)&t;
}

// ---------------------------------------------------------------------------
// Tensor-core 3x3 SAME conv, NHWC bf16, cp.async double-buffered.
// NEW: CTA = 2 rows x 64 oc, occupancy 2.  grid (64 rowpairs, 4 ocq, 2 br).
// smem: stageX[2][4][132][24] (50688) + Wt[2][9][64][24] (55296) = 105984
// ---------------------------------------------------------------------------
#define CONV_SMEM 105984

template <int CIN>
__global__ void __launch_bounds__(256, 2) conv_mma(
    const bf16* __restrict__ X, const bf16* __restrict__ Wb,
    const float* __restrict__ Bias, bf16* __restrict__ Y,
    long long Xz, long long Wz, long long Yz) {
    extern __shared__ char smem[];
    bf16 (*stageX)[4][132][24] = (bf16(*)[4][132][24])(smem);
    bf16 (*Wt)[9][64][24]      = (bf16(*)[9][64][24])(smem + 50688);
    bf16 (*stageO)[72]         = (bf16(*)[72])(smem);   // 256 x 72 bf16 = 36864

    int y0 = blockIdx.x * 2;
    int ocq = blockIdx.y;                    // 0..3 -> oc base ocq*64
    X += (size_t)blockIdx.z * Xz;
    Wb += (size_t)blockIdx.z * Wz;
    Bias += (size_t)blockIdx.z * 256;
    Y += (size_t)blockIdx.z * Yz;

    int tid = threadIdx.x;
    int lane = tid & 31, wid = tid >> 5;
    int g = lane >> 2, q = lane & 3;
    int mw = wid & 3, nw = wid >> 2;         // mw: 4 px-tiles of 64; nw: 2 oc-tiles of 32
    int mrow = mw >> 1, mx0 = (mw & 1) * 64;

    const int CH = CIN / 16;
    float acc[4][4][4] = {};

    auto load_chunk = [&](int buf, int ch) {
        int ic0 = ch * 16;
        for (int idx = tid; idx < 1056; idx += 256) {
            int r = idx / 264, rem = idx % 264;
            int pxi = rem >> 1, half = rem & 1;
            int gy = y0 + r - 1, gx = pxi - 1;
            bf16* dst = &stageX[buf][r][pxi][half * 8];
            if (gy >= 0 && gy < 128 && gx >= 0 && gx < 128) {
                const bf16* src = X + ((size_t)gy * IMW + gx) * CIN + ic0 + half * 8;
                CPA16((unsigned)__cvta_generic_to_shared(dst), src);
            } else {
                *(uint4*)dst = make_uint4(0u, 0u, 0u, 0u);
            }
        }
        for (int idx = tid; idx < 1152; idx += 256) {
            int tap = idx / 128, rem = idx % 128;
            int oc = rem >> 1, half = rem & 1;
            bf16* dst = &Wt[buf][tap][oc][half * 8];
            const bf16* src = Wb + ((size_t)tap * 256 + ocq * 64 + oc) * CIN + ic0 + half * 8;
            CPA16((unsigned)__cvta_generic_to_shared(dst), src);
        }
        CPA_COMMIT;
    };

    load_chunk(0, 0);
    int buf = 0;
    for (int ch = 0; ch < CH; ch++) {
        CPA_WAIT0;
        __syncthreads();
        if (ch + 1 < CH) load_chunk(buf ^ 1, ch + 1);
#pragma unroll
        for (int tap = 0; tap < 9; tap++) {
            int ky = tap / 3, kx = tap % 3;
            unsigned bfr[4][2];
#pragma unroll
            for (int nt = 0; nt < 4; nt++) {
                int oc = nw * 32 + nt * 8 + g;
                bfr[nt][0] = *(const unsigned*)&Wt[buf][tap][oc][q * 2];
                bfr[nt][1] = *(const unsigned*)&Wt[buf][tap][oc][q * 2 + 8];
            }
#pragma unroll
            for (int mt = 0; mt < 4; mt++) {
                int p0 = mx0 + mt * 16 + kx;
                unsigned af[4];
                af[0] = *(const unsigned*)&stageX[buf][mrow + ky][p0 + g][q * 2];
                af[1] = *(const unsigned*)&stageX[buf][mrow + ky][p0 + g + 8][q * 2];
                af[2] = *(const unsigned*)&stageX[buf][mrow + ky][p0 + g][q * 2 + 8];
                af[3] = *(const unsigned*)&stageX[buf][mrow + ky][p0 + g + 8][q * 2 + 8];
#pragma unroll
                for (int nt = 0; nt < 4; nt++) mma16816(acc[mt][nt], af, bfr[nt]);
            }
        }
        buf ^= 1;
    }

    // epilogue: bias + store NHWC (oc quarter of 64)
    __syncthreads();
#pragma unroll
    for (int mt = 0; mt < 4; mt++) {
#pragma unroll
        for (int nt = 0; nt < 4; nt++) {
            int m = mrow * 128 + mx0 + mt * 16 + g;
            int n = nw * 32 + nt * 8 + q * 2;
            float b0 = Bias[ocq * 64 + n];
            float b1 = Bias[ocq * 64 + n + 1];
            stageO[m][n]         = __float2bfloat16(acc[mt][nt][0] + b0);
            stageO[m][n + 1]     = __float2bfloat16(acc[mt][nt][1] + b1);
            stageO[m + 8][n]     = __float2bfloat16(acc[mt][nt][2] + b0);
            stageO[m + 8][n + 1] = __float2bfloat16(acc[mt][nt][3] + b1);
        }
    }
    __syncthreads();
    for (int idx = tid; idx < 2048; idx += 256) {
        int px = idx >> 3, v = idx & 7;
        uint4 val = *(const uint4*)&stageO[px][v * 8];
        *(uint4*)(Y + ((size_t)(y0 + (px >> 7)) * IMW + (px & 127)) * 256
                  + ocq * 64 + v * 8) = val;
    }
}

// ---------------------------------------------------------------------------
// Fused flash attention (Round-10 proven version: vT input, LDS B-frags)
// ---------------------------------------------------------------------------
#define FA_SMEM 225280
#define FA_KS   18432
#define FA_VT   55296
#define FA_AS   90112
#define L2E     1.44269504088896f

__global__ void __launch_bounds__(256, 1) fused_attn(
    const bf16* __restrict__ qkv, const bf16* __restrict__ vT,
    const float* __restrict__ Am, bf16* __restrict__ outp) {
    extern __shared__ char smem[];
    bf16 (*Qs)[72]       = (bf16(*)[72])(smem);
    bf16 (*Ks)[128][72]  = (bf16(*)[128][72])(smem + FA_KS);
    bf16 (*VTs)[64][136] = (bf16(*)[64][136])(smem + FA_VT);
    float (*As)[128][132] = (float(*)[128][132])(smem + FA_AS);

    int rb = blockIdx.x, h = blockIdx.y, br = blockIdx.z;
    qkv += (size_t)br * 1024 * 1536;
    vT += (size_t)br * 512 * 1024;
    outp += (size_t)br * 1024 * 512;

    int tid = threadIdx.x;
    int lane = tid & 31, wid = tid >> 5;
    int g = lane >> 2, q = lane & 3;
    int qrow = wid * 16;

    auto load_j = [&](int buf, int j) {
        int kbase = j * 128;
        for (int idx = tid; idx < 1024; idx += 256) {
            int r = idx >> 3, c = idx & 7;
            CPA16((unsigned)__cvta_generic_to_shared(&Ks[buf][r][c * 8]),
                  qkv + (size_t)(kbase + r) * 1536 + 512 + h * 64 + c * 8);
        }
        for (int idx = tid; idx < 1024; idx += 256) {
            int r = idx >> 4, c = idx & 15;
            CPA16((unsigned)__cvta_generic_to_shared(&VTs[buf][r][c * 8]),
                  vT + (size_t)(h * 64 + r) * 1024 + kbase + c * 8);
        }
        for (int idx = tid; idx < 4096; idx += 256) {
            int r = idx >> 5, c = idx & 31;
            CPA16((unsigned)__cvta_generic_to_shared(&As[buf][r][c * 4]),
                  Am + (size_t)(rb * 128 + r) * 1024 + kbase + c * 4);
        }
        CPA_COMMIT;
    };

    for (int idx = tid; idx < 1024; idx += 256) {
        int r = idx >> 3, c = idx & 7;
        CPA16((unsigned)__cvta_generic_to_shared(&Qs[r][c * 8]),
              qkv + (size_t)(rb * 128 + r) * 1536 + h * 64 + c * 8);
    }
    load_j(0, 0);

    float m0 = -1e30f, m1 = -1e30f, l0 = 0.f, l1 = 0.f;
    float acc_o[8][4] = {};

    for (int j = 0; j < 8; j++) {
        int buf = j & 1;
        if (j < 7) { load_j(buf ^ 1, j + 1); CPA_WAIT1; }
        else       { CPA_WAIT0; }
        __syncthreads();

        float s[16][4] = {};
#pragma unroll
        for (int ks = 0; ks < 4; ks++) {
            unsigned aq[4];
            aq[0] = *(const unsigned*)&Qs[qrow + g][ks * 16 + q * 2];
            aq[1] = *(const unsigned*)&Qs[qrow + g + 8][ks * 16 + q * 2];
            aq[2] = *(const unsigned*)&Qs[qrow + g][ks * 16 + q * 2 + 8];
            aq[3] = *(const unsigned*)&Qs[qrow + g + 8][ks * 16 + q * 2 + 8];
#pragma unroll
            for (int nt = 0; nt < 16; nt++) {
                unsigned bk[2];
                bk[0] = *(const unsigned*)&Ks[buf][nt * 8 + g][ks * 16 + q * 2];
                bk[1] = *(const unsigned*)&Ks[buf][nt * 8 + g][ks * 16 + q * 2 + 8];
                mma16816(s[nt], aq, bk);
            }
        }
#pragma unroll
        for (int nt = 0; nt < 16; nt++) {
            int col = nt * 8 + q * 2;
            s[nt][0] = s[nt][0] * 0.125f + As[buf][qrow + g][col];
            s[nt][1] = s[nt][1] * 0.125f + As[buf][qrow + g][col + 1];
            s[nt][2] = s[nt][2] * 0.125f + As[buf][qrow + g + 8][col];
            s[nt][3] = s[nt][3] * 0.125f + As[buf][qrow + g + 8][col + 1];
        }
        float mx0 = -1e30f, mx1 = -1e30f;
#pragma unroll
        for (int nt = 0; nt < 16; nt++) {
            mx0 = fmaxf(mx0, fmaxf(s[nt][0], s[nt][1]));
            mx1 = fmaxf(mx1, fmaxf(s[nt][2], s[nt][3]));
        }
#pragma unroll
        for (int o = 1; o <= 2; o <<= 1) {
            mx0 = fmaxf(mx0, __shfl_xor_sync(0xffffffffu, mx0, o));
            mx1 = fmaxf(mx1, __shfl_xor_sync(0xffffffffu, mx1, o));
        }
        float m0n = fmaxf(m0, mx0), m1n = fmaxf(m1, mx1);
        float c0 = exp2f((m0 - m0n) * L2E), c1 = exp2f((m1 - m1n) * L2E);
        float sum0 = 0.f, sum1 = 0.f;
        unsigned p[16][2];
#pragma unroll
        for (int nt = 0; nt < 16; nt++) {
            float p0 = exp2f((s[nt][0] - m0n) * L2E);
            float p1 = exp2f((s[nt][1] - m0n) * L2E);
            float p2 = exp2f((s[nt][2] - m1n) * L2E);
            float p3 = exp2f((s[nt][3] - m1n) * L2E);
            sum0 += p0 + p1;
            sum1 += p2 + p3;
            p[nt][0] = packbf(p0, p1);
            p[nt][1] = packbf(p2, p3);
        }
#pragma unroll
        for (int o = 1; o <= 2; o <<= 1) {
            sum0 += __shfl_xor_sync(0xffffffffu, sum0, o);
            sum1 += __shfl_xor_sync(0xffffffffu, sum1, o);
        }
        l0 = l0 * c0 + sum0;
        l1 = l1 * c1 + sum1;
        m0 = m0n; m1 = m1n;
#pragma unroll
        for (int nto = 0; nto < 8; nto++) {
            acc_o[nto][0] *= c0; acc_o[nto][1] *= c0;
            acc_o[nto][2] *= c1; acc_o[nto][3] *= c1;
        }
#pragma unroll
        for (int ks = 0; ks < 8; ks++) {
            unsigned ap[4] = {p[2 * ks][0], p[2 * ks][1], p[2 * ks + 1][0], p[2 * ks + 1][1]};
#pragma unroll
            for (int nto = 0; nto < 8; nto++) {
                unsigned bv[2];
                bv[0] = *(const unsigned*)&VTs[buf][nto * 8 + g][ks * 16 + q * 2];
                bv[1] = *(const unsigned*)&VTs[buf][nto * 8 + g][ks * 16 + q * 2 + 8];
                mma16816(acc_o[nto], ap, bv);
            }
        }
        __syncthreads();
    }

    float i0 = 1.f / l0, i1 = 1.f / l1;
    int row0 = rb * 128 + qrow + g, row1 = row0 + 8;
#pragma unroll
    for (int nto = 0; nto < 8; nto++) {
        int col = h * 64 + nto * 8 + q * 2;
        *(unsigned*)(outp + (size_t)row0 * 512 + col) = packbf(acc_o[nto][0] * i0, acc_o[nto][1] * i0);
        *(unsigned*)(outp + (size_t)row1 * 512 + col) = packbf(acc_o[nto][2] * i1, acc_o[nto][3] * i1);
    }
}

// ---------------------------------------------------------------------------
// Generic bf16 GEMM with 2-level z batching + optional aux relu-bf16 output
// ---------------------------------------------------------------------------
template <int BM, int BN, int WRM, int WRN>
__global__ void __launch_bounds__(256) gemm_bf16(
    int M, int N, int K,
    const bf16* __restrict__ A, int lda,
    const bf16* __restrict__ B, int ldb,
    void* __restrict__ Cv, int ldc,
    const float* __restrict__ bias,
    const float* __restrict__ res, int ldr,
    int flags, float alpha, int zmod,
    long long Az1, long long Az2, long long Bz1, long long Bz2,
    long long Cz1, long long Cz2, long long bz2, long long Rz2,
    bf16* __restrict__ aux, long long auxz2) {
    const int WM = BM / WRM, WN = BN / WRN;
    const int MT = WM / 16, NT = WN / 8;
    __shared__ __align__(16) bf16 As[BM][40];
    __shared__ __align__(16) bf16 Bs[BN][40];

    long long z = blockIdx.z;
    long long z1 = z % zmod, z2 = z / zmod;
    A += z1 * Az1 + z2 * Az2;
    B += z1 * Bz1 + z2 * Bz2;
    long long coff = z1 * Cz1 + z2 * Cz2;
    if (bias) bias += z2 * bz2;
    if (res) res += z2 * Rz2;
    if (aux) aux += z2 * auxz2;

    int m0 = blockIdx.y * BM, n0 = blockIdx.x * BN;
    int tid = threadIdx.x, lane = tid & 31, wid = tid >> 5;
    int g = lane >> 2, q = lane & 3;
    int wm0 = (wid % WRM) * WM, wn0 = (wid / WRM) * WN;

    float acc[MT][NT][4] = {};

    for (int k0 = 0; k0 < K; k0 += 32) {
        __syncthreads();
#pragma unroll
        for (int r = 0; r < BM * 4 / 256; r++) {
            int idx = tid + r * 256;
            int row = idx >> 2, quad = idx & 3;
            uint4 v = *(const uint4*)(A + (size_t)(m0 + row) * lda + k0 + quad * 8);
            *(uint4*)&As[row][quad * 8] = v;
        }
#pragma unroll
        for (int r = 0; r < BN * 4 / 256; r++) {
            int idx = tid + r * 256;
            int row = idx >> 2, quad = idx & 3;
            uint4 v = *(const uint4*)(B + (size_t)(n0 + row) * ldb + k0 + quad * 8);
            *(uint4*)&Bs[row][quad * 8] = v;
        }
        __syncthreads();
#pragma unroll
        for (int kk = 0; kk < 2; kk++) {
            unsigned af[MT][4], bfr[NT][2];
#pragma unroll
            for (int mt = 0; mt < MT; mt++) {
                int row = wm0 + mt * 16 + g;
                af[mt][0] = *(const unsigned*)&As[row][kk * 16 + q * 2];
                af[mt][1] = *(const unsigned*)&As[row + 8][kk * 16 + q * 2];
                af[mt][2] = *(const unsigned*)&As[row][kk * 16 + q * 2 + 8];
                af[mt][3] = *(const unsigned*)&As[row + 8][kk * 16 + q * 2 + 8];
            }
#pragma unroll
            for (int nt = 0; nt < NT; nt++) {
                int col = wn0 + nt * 8 + g;
                bfr[nt][0] = *(const unsigned*)&Bs[col][kk * 16 + q * 2];
                bfr[nt][1] = *(const unsigned*)&Bs[col][kk * 16 + q * 2 + 8];
            }
#pragma unroll
            for (int mt = 0; mt < MT; mt++)
#pragma unroll
                for (int nt = 0; nt < NT; nt++) mma16816(acc[mt][nt], af[mt], bfr[nt]);
        }
    }

    float* Cf = (float*)Cv + coff;
    bf16* Ch = (bf16*)Cv + coff;
#pragma unroll
    for (int mt = 0; mt < MT; mt++) {
#pragma unroll
        for (int nt = 0; nt < NT; nt++) {
#pragma unroll
            for (int e = 0; e < 4; e++) {
                int row = m0 + wm0 + mt * 16 + g + (e >> 1) * 8;
                int col = n0 + wn0 + nt * 8 + q * 2 + (e & 1);
                float v = acc[mt][nt][e] * alpha;
                if (flags & EF_RES)  v += res[(size_t)row * ldr + col];
                if (flags & EF_BIAS) v += bias[col];
                if (flags & EF_RELU) v = fmaxf(v, 0.f);
                if (flags & EF_GELU) v = 0.5f * v * (1.f + erff(v * 0.70710678118654752f));
                if (flags & EF_F16OUT) Ch[(size_t)row * ldc + col] = __float2bfloat16(v);
                else                   Cf[(size_t)row * ldc + col] = v;
                if (flags & EF_AUX)
                    aux[(size_t)row * 512 + col] = __float2bfloat16(fmaxf(v, 0.f));
            }
        }
    }
}

// ---------------------------------------------------------------------------
// fp32 GEMM (head only)
// ---------------------------------------------------------------------------
__global__ void __launch_bounds__(256) gemm_nn(
    int M, int N, int K,
    const float* __restrict__ A, int lda,
    const float* __restrict__ B, int ldb,
    float* __restrict__ C, int ldc,
    const float* __restrict__ bias, int flags) {
    __shared__ __align__(16) float As[16][68];
    __shared__ __align__(16) float Bs[16][68];
    int n0 = blockIdx.x * 64, m0 = blockIdx.y * 64;
    int tid = threadIdx.x, tx = tid & 15, ty = tid >> 4;
    int arow = tid >> 2, akg = tid & 3;
    int brow = tid >> 4, bcg = tid & 15;
    float acc[4][4] = {};
    for (int k0 = 0; k0 < K; k0 += 16) {
        float4 av = *(const float4*)(A + (size_t)(m0 + arow) * lda + k0 + 4 * akg);
        float4 bv = *(const float4*)(B + (size_t)(k0 + brow) * ldb + n0 + 4 * bcg);
        __syncthreads();
        As[4 * akg + 0][arow] = av.x; As[4 * akg + 1][arow] = av.y;
        As[4 * akg + 2][arow] = av.z; As[4 * akg + 3][arow] = av.w;
        *(float4*)&Bs[brow][4 * bcg] = bv;
        __syncthreads();
#pragma unroll
        for (int kk = 0; kk < 16; kk++) {
            float4 a = *(const float4*)&As[kk][ty * 4];
            float4 b = *(const float4*)&Bs[kk][tx * 4];
            acc[0][0] += a.x * b.x; acc[0][1] += a.x * b.y;
            acc[0][2] += a.x * b.z; acc[0][3] += a.x * b.w;
            acc[1][0] += a.y * b.x; acc[1][1] += a.y * b.y;
            acc[1][2] += a.y * b.z; acc[1][3] += a.y * b.w;
            acc[2][0] += a.z * b.x; acc[2][1] += a.z * b.y;
            acc[2][2] += a.z * b.z; acc[2][3] += a.z * b.w;
            acc[3][0] += a.w * b.x; acc[3][1] += a.w * b.y;
            acc[3][2] += a.w * b.z; acc[3][3] += a.w * b.w;
        }
    }
#pragma unroll
    for (int mi = 0; mi < 4; mi++) {
        int row = m0 + ty * 4 + mi;
#pragma unroll
        for (int ni = 0; ni < 4; ni++) {
            int col = n0 + tx * 4 + ni;
            float v = acc[mi][ni];
            if (flags & EF_BIAS) v += bias[col];
            if (flags & EF_RELU) v = fmaxf(v, 0.f);
            C[(size_t)row * ldc + col] = v;
        }
    }
}

// ---------------------------------------------------------------------------
// (x += pos?); out = LN(x)*g + b -> bf16.   grid (1024, 2), block 256
// ---------------------------------------------------------------------------
__global__ void addpos_ln(float* __restrict__ x, const float* __restrict__ pos,
                          const float* __restrict__ g, const float* __restrict__ b,
                          bf16* __restrict__ out) {
    size_t rg = (size_t)blockIdx.y * 1024 + blockIdx.x;
    int br = blockIdx.y, t = threadIdx.x;
    float v = x[rg * 256 + t];
    if (pos) {
        v += pos[rg * 256 + t];
        x[rg * 256 + t] = v;
    }
    float mean = blockReduceSum(v) * (1.f / 256.f);
    float d = v - mean;
    float var = blockReduceSum(d * d) * (1.f / 256.f);
    out[rg * 256 + t] = __float2bfloat16(d * rsqrtf(var + 1e-5f) * g[br * 256 + t] + b[br * 256 + t]);
}

__global__ void absdiff(const float* __restrict__ a, const float* __restrict__ b,
                        float* __restrict__ o) {
    int i = blockIdx.x * 256 + threadIdx.x;
    o[i] = fabsf(a[i] - b[i]);
}

__global__ void head2k(const float* __restrict__ hd, const float* __restrict__ W2,
                       const float* __restrict__ b2, float* __restrict__ out) {
    int row = blockIdx.x, t = threadIdx.x;
    float v = hd[row * 128 + t];
    float l0 = v * W2[2 * t], l1 = v * W2[2 * t + 1];
    __shared__ float s0[4], s1[4];
    int lane = t & 31, w = t >> 5;
#pragma unroll
    for (int o = 16; o; o >>= 1) {
        l0 += __shfl_xor_sync(0xffffffffu, l0, o);
        l1 += __shfl_xor_sync(0xffffffffu, l1, o);
    }
    if (lane == 0) { s0[w] = l0; s1[w] = l1; }
    __syncthreads();
    if (t == 0) {
        float a = s0[0] + s0[1] + s0[2] + s0[3] + b2[0];
        float c = s1[0] + s1[1] + s1[2] + s1[3] + b2[1];
        float m = fmaxf(a, c);
        float e0 = expf(a - m), e1 = expf(c - m);
        float inv = 1.f / (e0 + e1);
        out[row * 2 + 0] = e0 * inv;
        out[row * 2 + 1] = e1 * inv;
    }
}

// ---------------------------------------------------------------------------
// Host orchestration: two-stream fork-join, record-before-wait issue order
// ---------------------------------------------------------------------------
extern "C" void kernel_launch(void* const* d_in, const int* in_sizes, int n_in,
                              void* d_out, int out_size) {
    const float* T[2]     = {(const float*)d_in[0], (const float*)d_in[1]};
    const float* Q        = (const float*)d_in[2];
    const float* Am       = (const float*)d_in[3];
    const float* convW_in = (const float*)d_in[4];
    const float* convB_in = (const float*)d_in[5];
    const float* convW    = (const float*)d_in[6];
    const float* convB    = (const float*)d_in[7];
    const float* fc0_b    = (const float*)d_in[9];
    const float* fc_b     = (const float*)d_in[11];
    const float* pos      = (const float*)d_in[12];
    const float* ln1_g    = (const float*)d_in[13];
    const float* ln1_b    = (const float*)d_in[14];
    const float* out_b    = (const float*)d_in[17];
    const float* ln2_g    = (const float*)d_in[18];
    const float* ln2_b    = (const float*)d_in[19];
    const float* ff_b1    = (const float*)d_in[21];
    const float* ff_b2    = (const float*)d_in[23];
    const float* head_W1  = (const float*)d_in[24];
    const float* head_b1  = (const float*)d_in[25];
    const float* head_W2  = (const float*)d_in[26];
    const float* head_b2  = (const float*)d_in[27];
    float* outp = (float*)d_out;

    void* p;
    cudaGetSymbolAddress(&p, g_convb);  bf16* convb = (bf16*)p;
    cudaGetSymbolAddress(&p, g_tb);     bf16* tb = (bf16*)p;
    cudaGetSymbolAddress(&p, g_wb0);    bf16* wb0 = (bf16*)p;
    cudaGetSymbolAddress(&p, g_wbN);    bf16* wbN = (bf16*)p;
    cudaGetSymbolAddress(&p, g_wenc);   bf16* wenc = (bf16*)p;
    cudaGetSymbolAddress(&p, g_catb);   bf16* catb = (bf16*)p;
    cudaGetSymbolAddress(&p, g_hb);     bf16* hb = (bf16*)p;
    cudaGetSymbolAddress(&p, g_qkvb);   bf16* qkvb = (bf16*)p;
    cudaGetSymbolAddress(&p, g_vT);     bf16* vT = (bf16*)p;
    cudaGetSymbolAddress(&p, g_attnob); bf16* attnob = (bf16*)p;
    cudaGetSymbolAddress(&p, g_ff1b);   bf16* ff1b = (bf16*)p;
    cudaGetSymbolAddress(&p, g_x);      float* x = (float*)p;
    cudaGetSymbolAddress(&p, g_dd);     float* dd = (float*)p;
    cudaGetSymbolAddress(&p, g_hd);     float* hd = (float*)p;

    cudaFuncSetAttribute(conv_mma<224>, cudaFuncAttributeMaxDynamicSharedMemorySize, CONV_SMEM);
    cudaFuncSetAttribute(conv_mma<256>, cudaFuncAttributeMaxDynamicSharedMemorySize, CONV_SMEM);
    cudaFuncSetAttribute(fused_attn, cudaFuncAttributeMaxDynamicSharedMemorySize, FA_SMEM);

    // one-time host-side resources (no device memory)
    static cudaStream_t s1 = nullptr;
    static cudaEvent_t evFork, evConv[NSTG], evCt[NSTG];
    if (!s1) {
        cudaStreamCreateWithFlags(&s1, cudaStreamNonBlocking);
        cudaEventCreateWithFlags(&evFork, cudaEventDisableTiming);
        for (int i = 0; i < NSTG; i++) {
            cudaEventCreateWithFlags(&evConv[i], cudaEventDisableTiming);
            cudaEventCreateWithFlags(&evCt[i], cudaEventDisableTiming);
        }
    }

    const long long PP = 4194304;

    // ---- fork ----
    cudaEventRecord(evFork, 0);
    cudaStreamWaitEvent(s1, evFork, 0);

    // ---- conv chain prolog + conv0, conv1 ----
    chw2hwc<<<dim3(512, 7), dim3(32, 8), 0, s1>>>(T[0], tb, 224);
    chw2hwc<<<dim3(512, 7), dim3(32, 8), 0, s1>>>(T[1], tb + 16384ll * 224, 224);
    repack_w<224><<<4032, 256, 0, s1>>>(convW_in, wb0);
    conv_mma<224><<<dim3(64, 4, 2), 256, CONV_SMEM, s1>>>(
        tb, wb0, convB_in, convb, 16384ll * 224, 9ll * 256 * 224, 2 * PP);
    cudaEventRecord(evConv[0], s1);
    repack_w<256><<<23040, 256, 0, s1>>>(convW, wbN);
    conv_mma<256><<<dim3(64, 4, 2), 256, CONV_SMEM, s1>>>(
        convb, wbN, convB, convb + PP, 2 * PP, 9ll * 256 * 256, 2 * PP);
    cudaEventRecord(evConv[1], s1);

    // ---- encoder prolog (main stream) ----
    build_sp<<<1024, 256>>>(Q);
    wconv_t<<<dim3(48, 8, 12), dim3(32, 8)>>>((const float*)d_in[15], wenc + OFF_QKV, 256, 1536);
    wconv_t<<<dim3(8, 16, 12), dim3(32, 8)>>>((const float*)d_in[16], wenc + OFF_O, 512, 256);
    wconv_t<<<dim3(16, 8, 12), dim3(32, 8)>>>((const float*)d_in[20], wenc + OFF_W1, 256, 512);
    wconv_t<<<dim3(8, 16, 12), dim3(32, 8)>>>((const float*)d_in[22], wenc + OFF_W2, 512, 256);
    wconv_t<<<dim3(8, 15, 2), dim3(32, 8)>>>((const float*)d_in[8], wenc + OFF_FC0, 480, 256);
    wconv_t<<<dim3(8, 16, 10), dim3(32, 8)>>>((const float*)d_in[10], wenc + OFF_FC, 512, 256);
    ct_mean_f32<<<dim3(224, 4), 256>>>(T[0], catb, 256);
    ct_mean_f32<<<dim3(224, 4), 256>>>(T[1], catb + 524288, 256);

    for (int s = 0; s < NSTG; s++) {
        int sbase = s * 2;
        cudaStreamWaitEvent(0, evConv[s], 0);
        ct_nhwc<<<dim3(1024, 2), 256>>>(convb + (s & 1) * PP, 2 * PP, catb, 524288);
        cudaEventRecord(evCt[s], 0);
        if (s + 2 < NSTG) {
            int cw = (s + 1) * 2;
            cudaStreamWaitEvent(s1, evCt[s], 0);
            conv_mma<256><<<dim3(64, 4, 2), 256, CONV_SMEM, s1>>>(
                convb + ((s + 1) & 1) * PP, wbN + (size_t)cw * 9 * 256 * 256,
                convB + cw * 256, convb + (s & 1) * PP, 2 * PP, 9ll * 256 * 256, 2 * PP);
            cudaEventRecord(evConv[s + 2], s1);
        }
        if (s == 0) {
            gemm_bf16<64, 64, 2, 4><<<dim3(4, 16, 2), 256>>>(
                1024, 256, 480, catb, 512, wenc + OFF_FC0, 480, x, 256,
                fc0_b, nullptr, 0, EF_BIAS, 1.f, 1,
                0, 524288, 0, 122880, 0, 262144, 256, 0, nullptr, 0);
        } else {
            int cw = (s - 1) * 2;
            gemm_bf16<64, 64, 2, 4><<<dim3(4, 16, 2), 256>>>(
                1024, 256, 512, catb, 512, wenc + OFF_FC + (size_t)cw * 131072, 512, x, 256,
                fc_b + cw * 256, nullptr, 0, EF_BIAS, 1.f, 1,
                0, 524288, 0, 131072, 0, 262144, 256, 0, nullptr, 0);
        }
        addpos_ln<<<dim3(1024, 2), 256>>>(x, pos + (size_t)sbase * 262144,
                                          ln1_g + sbase * 256, ln1_b + sbase * 256, hb);
        // QK part: N=1024 (single wave, 128 CTAs)
        gemm_bf16<128, 128, 2, 4><<<dim3(8, 8, 2), 256>>>(
            1024, 1024, 256, hb, 256, wenc + OFF_QKV + (size_t)sbase * 393216, 256,
            qkvb, 1536, nullptr, nullptr, 0, EF_F16OUT, 1.f, 1,
            0, 262144, 0, 393216, 0, 1572864, 0, 0, nullptr, 0);
        // V^T direct: vT[dh][token] = Wv^T @ h^T  (M=512, N=1024)
        gemm_bf16<128, 128, 2, 4><<<dim3(8, 4, 2), 256>>>(
            512, 1024, 256, wenc + OFF_QKV + (size_t)sbase * 393216 + 1024 * 256, 256,
            hb, 256, vT, 1024, nullptr, nullptr, 0, EF_F16OUT, 1.f, 1,
            0, 393216, 0, 262144, 0, 524288, 0, 0, nullptr, 0);
        fused_attn<<<dim3(8, 8, 2), 256, FA_SMEM>>>(qkvb, vT, Am, attnob);
        gemm_bf16<64, 64, 2, 4><<<dim3(4, 16, 2), 256>>>(
            1024, 256, 512, attnob, 512, wenc + OFF_O + (size_t)sbase * 131072, 512, x, 256,
            out_b + sbase * 256, x, 256, EF_BIAS | EF_RES, 1.f, 1,
            0, 524288, 0, 131072, 0, 262144, 256, 262144, nullptr, 0);
        addpos_ln<<<dim3(1024, 2), 256>>>(x, nullptr,
                                          ln2_g + sbase * 256, ln2_b + sbase * 256, hb);
        gemm_bf16<64, 64, 2, 4><<<dim3(8, 16, 2), 256>>>(
            1024, 512, 256, hb, 256, wenc + OFF_W1 + (size_t)sbase * 131072, 256,
            ff1b, 512, ff_b1 + sbase * 512, nullptr, 0,
            EF_BIAS | EF_GELU | EF_F16OUT, 1.f, 1,
            0, 262144, 0, 131072, 0, 524288, 512, 0, nullptr, 0);
        gemm_bf16<64, 64, 2, 4><<<dim3(4, 16, 2), 256>>>(
            1024, 256, 512, ff1b, 512, wenc + OFF_W2 + (size_t)sbase * 131072, 512, x, 256,
            ff_b2 + sbase * 256, x, 256, EF_BIAS | EF_RES | EF_AUX, 1.f, 1,
            0, 524288, 0, 131072, 0, 262144, 256, 262144, catb + 256, 524288);
    }

    // ---- head ----
    absdiff<<<1024, 256>>>(x, x + 262144, dd);
    gemm_nn<<<dim3(2, 16), 256>>>(1024, 128, 256, dd, 256, head_W1, 128,
                                  hd, 128, head_b1, EF_BIAS | EF_RELU);
    head2k<<<1024, 128>>>(hd, head_W2, head_b2, outp);
}

// round 15
// speedup vs baseline: 1.0300x; 1.0300x over previous
#include <cuda_runtime.h>
#include <cuda_bf16.h>
#include <math.h>

#define SPX   1024
#define HWPX  16384
#define IMW   128
#define NSTG  6

#define EF_BIAS   1
#define EF_RELU   2
#define EF_GELU   4
#define EF_RES    8
#define EF_F16OUT 16
#define EF_AUX    32

typedef __nv_bfloat16 bf16;

// ---------------------------------------------------------------------------
// Scratch
// ---------------------------------------------------------------------------
__device__ bf16  g_convb[4ull * 16384 * 256];    // NHWC activations [slab*2+br]
__device__ bf16  g_tb[2ull * 16384 * 224];       // NHWC bf16 copies of T1/T2
__device__ bf16  g_wb0[2ull * 9 * 256 * 224];    // stage-0 conv weights
__device__ bf16  g_wbN[10ull * 9 * 256 * 256];   // stage-1..5 conv weights
__device__ bf16  g_wenc[11000832];               // transposed encoder/fc weights
__device__ bf16  g_amb[1024 * 1024];             // bf16 copy of attention bias A
__device__ bf16  g_catb[2ull * 1024 * 512];
__device__ bf16  g_hb[2ull * 1024 * 256];
__device__ bf16  g_qkvb[2ull * 1024 * 1536];
__device__ bf16  g_vT[2ull * 512 * 1024];
__device__ bf16  g_attnob[2ull * 1024 * 512];
__device__ bf16  g_ff1b[2ull * 1024 * 512];
__device__ float g_x[2ull * 1024 * 256];
__device__ float g_dd[1024 * 256];
__device__ float g_hd[1024 * 128];
__device__ int   g_splist[1024 * 64];
__device__ int   g_spcnt[1024];

#define OFF_QKV 0
#define OFF_O   4718592
#define OFF_W1  6291456
#define OFF_W2  7864320
#define OFF_FC0 9437184
#define OFF_FC  9682944

// ---------------------------------------------------------------------------
// cp.async helpers
// ---------------------------------------------------------------------------
#define CPA16(dst, src) \
    asm volatile("cp.async.cg.shared.global [%0], [%1], 16;\n" ::"r"(dst), "l"(src))
#define CPA_COMMIT asm volatile("cp.async.commit_group;\n")
#define CPA_WAIT0  asm volatile("cp.async.wait_group 0;\n")
#define CPA_WAIT1  asm volatile("cp.async.wait_group 1;\n")

// ---------------------------------------------------------------------------
// Block reductions
// ---------------------------------------------------------------------------
__device__ __forceinline__ float blockReduceSum(float v) {
    __shared__ float sh[8];
    int lane = threadIdx.x & 31, w = threadIdx.x >> 5;
#pragma unroll
    for (int o = 16; o; o >>= 1) v += __shfl_xor_sync(0xffffffffu, v, o);
    if (lane == 0) sh[w] = v;
    __syncthreads();
    float r = (threadIdx.x < 8) ? sh[threadIdx.x] : 0.f;
    if (w == 0) {
#pragma unroll
        for (int o = 4; o; o >>= 1) r += __shfl_xor_sync(0xffffffffu, r, o);
        if (lane == 0) sh[0] = r;
    }
    __syncthreads();
    float out = sh[0];
    __syncthreads();
    return out;
}

// ---------------------------------------------------------------------------
// Superpixel list builder
// ---------------------------------------------------------------------------
__global__ void build_sp(const float* __restrict__ Q) {
    int s = blockIdx.x;
    __shared__ int wcnt[8];
    __shared__ int cnt;
    if (threadIdx.x == 0) cnt = 0;
    __syncthreads();
    int lane = threadIdx.x & 31, warp = threadIdx.x >> 5;
    for (int base = 0; base < HWPX; base += 256) {
        int p = base + threadIdx.x;
        bool m = Q[(size_t)p * SPX + s] > 0.5f;
        unsigned bal = __ballot_sync(0xffffffffu, m);
        if (lane == 0) wcnt[warp] = __popc(bal);
        __syncthreads();
        int off = cnt;
        for (int w = 0; w < warp; w++) off += wcnt[w];
        off += __popc(bal & ((1u << lane) - 1u));
        if (m && off < 64) g_splist[s * 64 + off] = p;
        __syncthreads();
        if (threadIdx.x == 0) {
            int t = 0;
            for (int w = 0; w < 8; w++) t += wcnt[w];
            cnt += t;
        }
        __syncthreads();
    }
    if (threadIdx.x == 0) g_spcnt[s] = cnt < 64 ? cnt : 64;
}

// ---------------------------------------------------------------------------
// ct pooling (MLP-16 fast path; identical ascending add order)
// ---------------------------------------------------------------------------
__global__ void ct_nhwc(const bf16* __restrict__ img, long long imgz,
                        bf16* __restrict__ out, long long outz) {
    int s = blockIdx.x, c = threadIdx.x;
    img += (size_t)blockIdx.y * imgz;
    out += (size_t)blockIdx.y * outz;
    int cnt = g_spcnt[s];
    const int* lst = &g_splist[s * 64];
    float sum = 0.f;
    if (cnt == 16) {
        int idxs[16];
#pragma unroll
        for (int i = 0; i < 16; i++) idxs[i] = lst[i];
        float v[16];
#pragma unroll
        for (int i = 0; i < 16; i++)
            v[i] = __bfloat162float(img[(size_t)idxs[i] * 256 + c]);
#pragma unroll
        for (int i = 0; i < 16; i++) sum += v[i];
    } else {
        for (int i = 0; i < cnt; i++)
            sum += __bfloat162float(img[(size_t)lst[i] * 256 + c]);
    }
    out[(size_t)s * 512 + c] = __float2bfloat16(fmaxf(sum / (float)cnt, 0.f));
}

__global__ void ct_mean_f32(const float* __restrict__ img, bf16* __restrict__ out,
                            int coloff) {
    int c = blockIdx.x;
    int s = blockIdx.y * 256 + threadIdx.x;
    int cnt = g_spcnt[s];
    const int* lst = &g_splist[s * 64];
    float sum = 0.f;
    for (int i = 0; i < cnt; i++) sum += img[(size_t)c * HWPX + lst[i]];
    out[(size_t)s * 512 + coloff + c] = __float2bfloat16(fmaxf(sum / (float)cnt, 0.f));
}

// NCHW fp32 -> NHWC bf16 transpose. grid (512, 7), block (32,8).
__global__ void chw2hwc(const float* __restrict__ in, bf16* __restrict__ out, int C) {
    __shared__ float sm[32][33];
    int p0 = blockIdx.x * 32, c0 = blockIdx.y * 32;
    int tx = threadIdx.x, ty = threadIdx.y;
#pragma unroll
    for (int j = 0; j < 4; j++)
        sm[ty + 8 * j][tx] = in[(size_t)(c0 + ty + 8 * j) * HWPX + p0 + tx];
    __syncthreads();
#pragma unroll
    for (int j = 0; j < 4; j++)
        out[(size_t)(p0 + ty + 8 * j) * C + c0 + tx] = __float2bfloat16(sm[tx][ty + 8 * j]);
}

__global__ void f32_to_bf16(const float* __restrict__ in, bf16* __restrict__ out) {
    int i = blockIdx.x * 256 + threadIdx.x;
    out[i] = __float2bfloat16(in[i]);
}

// conv weight repack: [z][oc][ic][3][3] f32 -> [z][tap][oc][ic] bf16
template <int CIN>
__global__ void repack_w(const float* __restrict__ W, bf16* __restrict__ out) {
    int idx = blockIdx.x * 256 + threadIdx.x;
    int t = idx / (256 * CIN);
    int z = t / 9, tap = t % 9;
    int rem = idx - t * 256 * CIN;
    int oc = rem / CIN;
    int ic = rem - oc * CIN;
    out[idx] = __float2bfloat16(W[(size_t)z * 9 * 256 * CIN + ((size_t)oc * CIN + ic) * 9 + tap]);
}

// batched transpose+convert: in [Z][K][N] f32 -> out [Z][N][K] bf16
__global__ void wconv_t(const float* __restrict__ in, bf16* __restrict__ out,
                        int K, int N) {
    __shared__ float sm[32][33];
    int n0 = blockIdx.x * 32, k0 = blockIdx.y * 32;
    const float* inz = in + (size_t)blockIdx.z * K * N;
    bf16* outz = out + (size_t)blockIdx.z * K * N;
    int tx = threadIdx.x, ty = threadIdx.y;
#pragma unroll
    for (int j = 0; j < 4; j++)
        sm[ty + 8 * j][tx] = inz[(size_t)(k0 + ty + 8 * j) * N + n0 + tx];
    __syncthreads();
#pragma unroll
    for (int j = 0; j < 4; j++)
        outz[(size_t)(n0 + ty + 8 * j) * K + k0 + tx] = __float2bfloat16(sm[tx][ty + 8 * j]);
}

// transpose V slice of qkv -> vT.  grid (16, 32, 2), block (32, 8).
__global__ void transpose_v(const bf16* __restrict__ qkv, bf16* __restrict__ vT) {
    __shared__ bf16 sm[32][33];
    qkv += (size_t)blockIdx.z * 1024 * 1536;
    vT += (size_t)blockIdx.z * 512 * 1024;
    int c0 = blockIdx.x * 32, m0 = blockIdx.y * 32;
    int tx = threadIdx.x, ty = threadIdx.y;
#pragma unroll
    for (int j = 0; j < 4; j++)
        sm[ty + 8 * j][tx] = qkv[(size_t)(m0 + ty + 8 * j) * 1536 + 1024 + c0 + tx];
    __syncthreads();
#pragma unroll
    for (int j = 0; j < 4; j++)
        vT[(size_t)(c0 + ty + 8 * j) * 1024 + m0 + tx] = sm[tx][ty + 8 * j];
}

// ---------------------------------------------------------------------------
// mma helpers
// ---------------------------------------------------------------------------
__device__ __forceinline__ void mma16816(float* c, const unsigned* a, const unsigned* b) {
    asm volatile(
        "mma.sync.aligned.m16n8k16.row.col.f32.bf16.bf16.f32 "
        "{%0,%1,%2,%3}, {%4,%5,%6,%7}, {%8,%9}, {%0,%1,%2,%3};\n"
        : "+f"(c[0]), "+f"(c[1]), "+f"(c[2]), "+f"(c[3])
        : "r"(a[0]), "r"(a[1]), "r"(a[2]), "r"(a[3]), "r"(b[0]), "r"(b[1]));
}

__device__ __forceinline__ unsigned packbf(float a, float b) {
    __nv_bfloat162 t = __floats2bfloat162_rn(a, b);
    return *(unsigned*)&t;
}

// ---------------------------------------------------------------------------
// Tensor-core 3x3 SAME conv, NHWC bf16 (R12-proven: 2 rows x 128 oc, occ 1)
// ---------------------------------------------------------------------------
#define CONV_SMEM 161280

template <int CIN>
__global__ void __launch_bounds__(256, 1) conv_mma(
    const bf16* __restrict__ X, const bf16* __restrict__ Wb,
    const float* __restrict__ Bias, bf16* __restrict__ Y,
    long long Xz, long long Wz, long long Yz) {
    extern __shared__ char smem[];
    bf16 (*stageX)[4][132][24] = (bf16(*)[4][132][24])(smem);
    bf16 (*Wt)[9][128][24]     = (bf16(*)[9][128][24])(smem + 50688);
    bf16 (*stageO)[136]        = (bf16(*)[136])(smem);

    int y0 = blockIdx.x * 2;
    int ochalf = blockIdx.y;
    X += (size_t)blockIdx.z * Xz;
    Wb += (size_t)blockIdx.z * Wz;
    Bias += (size_t)blockIdx.z * 256;
    Y += (size_t)blockIdx.z * Yz;

    int tid = threadIdx.x;
    int lane = tid & 31, wid = tid >> 5;
    int g = lane >> 2, q = lane & 3;
    int mw = wid & 3, nw = wid >> 2;
    int mrow = mw >> 1, mx0 = (mw & 1) * 64;

    const int CH = CIN / 16;
    float acc[4][8][4] = {};

    auto load_chunk = [&](int buf, int ch) {
        int ic0 = ch * 16;
        for (int idx = tid; idx < 1056; idx += 256) {
            int r = idx / 264, rem = idx % 264;
            int pxi = rem >> 1, half = rem & 1;
            int gy = y0 + r - 1, gx = pxi - 1;
            bf16* dst = &stageX[buf][r][pxi][half * 8];
            if (gy >= 0 && gy < 128 && gx >= 0 && gx < 128) {
                const bf16* src = X + ((size_t)gy * IMW + gx) * CIN + ic0 + half * 8;
                CPA16((unsigned)__cvta_generic_to_shared(dst), src);
            } else {
                *(uint4*)dst = make_uint4(0u, 0u, 0u, 0u);
            }
        }
        for (int idx = tid; idx < 2304; idx += 256) {
            int tap = idx / 256, rem = idx % 256;
            int oc = rem >> 1, half = rem & 1;
            bf16* dst = &Wt[buf][tap][oc][half * 8];
            const bf16* src = Wb + ((size_t)tap * 256 + ochalf * 128 + oc) * CIN + ic0 + half * 8;
            CPA16((unsigned)__cvta_generic_to_shared(dst), src);
        }
        CPA_COMMIT;
    };

    load_chunk(0, 0);
    int buf = 0;
    for (int ch = 0; ch < CH; ch++) {
        CPA_WAIT0;
        __syncthreads();
        if (ch + 1 < CH) load_chunk(buf ^ 1, ch + 1);
#pragma unroll
        for (int tap = 0; tap < 9; tap++) {
            int ky = tap / 3, kx = tap % 3;
            unsigned bfr[8][2];
#pragma unroll
            for (int nt = 0; nt < 8; nt++) {
                int oc = nw * 64 + nt * 8 + g;
                bfr[nt][0] = *(const unsigned*)&Wt[buf][tap][oc][q * 2];
                bfr[nt][1] = *(const unsigned*)&Wt[buf][tap][oc][q * 2 + 8];
            }
#pragma unroll
            for (int mt = 0; mt < 4; mt++) {
                int p0 = mx0 + mt * 16 + kx;
                unsigned af[4];
                af[0] = *(const unsigned*)&stageX[buf][mrow + ky][p0 + g][q * 2];
                af[1] = *(const unsigned*)&stageX[buf][mrow + ky][p0 + g + 8][q * 2];
                af[2] = *(const unsigned*)&stageX[buf][mrow + ky][p0 + g][q * 2 + 8];
                af[3] = *(const unsigned*)&stageX[buf][mrow + ky][p0 + g + 8][q * 2 + 8];
#pragma unroll
                for (int nt = 0; nt < 8; nt++) mma16816(acc[mt][nt], af, bfr[nt]);
            }
        }
        buf ^= 1;
    }

    __syncthreads();
#pragma unroll
    for (int mt = 0; mt < 4; mt++) {
#pragma unroll
        for (int nt = 0; nt < 8; nt++) {
            int m = mrow * 128 + mx0 + mt * 16 + g;
            int n = nw * 64 + nt * 8 + q * 2;
            float b0 = Bias[ochalf * 128 + n];
            float b1 = Bias[ochalf * 128 + n + 1];
            stageO[m][n]         = __float2bfloat16(acc[mt][nt][0] + b0);
            stageO[m][n + 1]     = __float2bfloat16(acc[mt][nt][1] + b1);
            stageO[m + 8][n]     = __float2bfloat16(acc[mt][nt][2] + b0);
            stageO[m + 8][n + 1] = __float2bfloat16(acc[mt][nt][3] + b1);
        }
    }
    __syncthreads();
    for (int idx = tid; idx < 4096; idx += 256) {
        int px = idx >> 4, v = idx & 15;
        uint4 val = *(const uint4*)&stageO[px][v * 8];
        *(uint4*)(Y + ((size_t)(y0 + (px >> 7)) * IMW + (px & 127)) * 256
                  + ochalf * 128 + v * 8) = val;
    }
}

// ---------------------------------------------------------------------------
// Fused flash attention; A bias now bf16 (halves dominant load traffic)
// smem: Qs[128][72] | Ks[2][128][72] | VTs[2][64][136] | As[2][128][136] bf16
// ---------------------------------------------------------------------------
#define FA_SMEM 159744
#define FA_KS   18432
#define FA_VT   55296
#define FA_AS   90112
#define L2E     1.44269504088896f

__global__ void __launch_bounds__(256, 1) fused_attn(
    const bf16* __restrict__ qkv, const bf16* __restrict__ vT,
    const bf16* __restrict__ Amb, bf16* __restrict__ outp) {
    extern __shared__ char smem[];
    bf16 (*Qs)[72]        = (bf16(*)[72])(smem);
    bf16 (*Ks)[128][72]   = (bf16(*)[128][72])(smem + FA_KS);
    bf16 (*VTs)[64][136]  = (bf16(*)[64][136])(smem + FA_VT);
    bf16 (*As)[128][136]  = (bf16(*)[128][136])(smem + FA_AS);

    int rb = blockIdx.x, h = blockIdx.y, br = blockIdx.z;
    qkv += (size_t)br * 1024 * 1536;
    vT += (size_t)br * 512 * 1024;
    outp += (size_t)br * 1024 * 512;

    int tid = threadIdx.x;
    int lane = tid & 31, wid = tid >> 5;
    int g = lane >> 2, q = lane & 3;
    int qrow = wid * 16;

    auto load_j = [&](int buf, int j) {
        int kbase = j * 128;
        for (int idx = tid; idx < 1024; idx += 256) {
            int r = idx >> 3, c = idx & 7;
            CPA16((unsigned)__cvta_generic_to_shared(&Ks[buf][r][c * 8]),
                  qkv + (size_t)(kbase + r) * 1536 + 512 + h * 64 + c * 8);
        }
        for (int idx = tid; idx < 1024; idx += 256) {
            int r = idx >> 4, c = idx & 15;
            CPA16((unsigned)__cvta_generic_to_shared(&VTs[buf][r][c * 8]),
                  vT + (size_t)(h * 64 + r) * 1024 + kbase + c * 8);
        }
        for (int idx = tid; idx < 2048; idx += 256) {
            int r = idx >> 4, c = idx & 15;
            CPA16((unsigned)__cvta_generic_to_shared(&As[buf][r][c * 8]),
                  Amb + (size_t)(rb * 128 + r) * 1024 + kbase + c * 8);
        }
        CPA_COMMIT;
    };

    for (int idx = tid; idx < 1024; idx += 256) {
        int r = idx >> 3, c = idx & 7;
        CPA16((unsigned)__cvta_generic_to_shared(&Qs[r][c * 8]),
              qkv + (size_t)(rb * 128 + r) * 1536 + h * 64 + c * 8);
    }
    load_j(0, 0);

    float m0 = -1e30f, m1 = -1e30f, l0 = 0.f, l1 = 0.f;
    float acc_o[8][4] = {};

    for (int j = 0; j < 8; j++) {
        int buf = j & 1;
        if (j < 7) { load_j(buf ^ 1, j + 1); CPA_WAIT1; }
        else       { CPA_WAIT0; }
        __syncthreads();

        float s[16][4] = {};
#pragma unroll
        for (int ks = 0; ks < 4; ks++) {
            unsigned aq[4];
            aq[0] = *(const unsigned*)&Qs[qrow + g][ks * 16 + q * 2];
            aq[1] = *(const unsigned*)&Qs[qrow + g + 8][ks * 16 + q * 2];
            aq[2] = *(const unsigned*)&Qs[qrow + g][ks * 16 + q * 2 + 8];
            aq[3] = *(const unsigned*)&Qs[qrow + g + 8][ks * 16 + q * 2 + 8];
#pragma unroll
            for (int nt = 0; nt < 16; nt++) {
                unsigned bk[2];
                bk[0] = *(const unsigned*)&Ks[buf][nt * 8 + g][ks * 16 + q * 2];
                bk[1] = *(const unsigned*)&Ks[buf][nt * 8 + g][ks * 16 + q * 2 + 8];
                mma16816(s[nt], aq, bk);
            }
        }
#pragma unroll
        for (int nt = 0; nt < 16; nt++) {
            int col = nt * 8 + q * 2;
            s[nt][0] = s[nt][0] * 0.125f + __bfloat162float(As[buf][qrow + g][col]);
            s[nt][1] = s[nt][1] * 0.125f + __bfloat162float(As[buf][qrow + g][col + 1]);
            s[nt][2] = s[nt][2] * 0.125f + __bfloat162float(As[buf][qrow + g + 8][col]);
            s[nt][3] = s[nt][3] * 0.125f + __bfloat162float(As[buf][qrow + g + 8][col + 1]);
        }
        float mx0 = -1e30f, mx1 = -1e30f;
#pragma unroll
        for (int nt = 0; nt < 16; nt++) {
            mx0 = fmaxf(mx0, fmaxf(s[nt][0], s[nt][1]));
            mx1 = fmaxf(mx1, fmaxf(s[nt][2], s[nt][3]));
        }
#pragma unroll
        for (int o = 1; o <= 2; o <<= 1) {
            mx0 = fmaxf(mx0, __shfl_xor_sync(0xffffffffu, mx0, o));
            mx1 = fmaxf(mx1, __shfl_xor_sync(0xffffffffu, mx1, o));
        }
        float m0n = fmaxf(m0, mx0), m1n = fmaxf(m1, mx1);
        float c0 = exp2f((m0 - m0n) * L2E), c1 = exp2f((m1 - m1n) * L2E);
        float sum0 = 0.f, sum1 = 0.f;
        unsigned p[16][2];
#pragma unroll
        for (int nt = 0; nt < 16; nt++) {
            float p0 = exp2f((s[nt][0] - m0n) * L2E);
            float p1 = exp2f((s[nt][1] - m0n) * L2E);
            float p2 = exp2f((s[nt][2] - m1n) * L2E);
            float p3 = exp2f((s[nt][3] - m1n) * L2E);
            sum0 += p0 + p1;
            sum1 += p2 + p3;
            p[nt][0] = packbf(p0, p1);
            p[nt][1] = packbf(p2, p3);
        }
#pragma unroll
        for (int o = 1; o <= 2; o <<= 1) {
            sum0 += __shfl_xor_sync(0xffffffffu, sum0, o);
            sum1 += __shfl_xor_sync(0xffffffffu, sum1, o);
        }
        l0 = l0 * c0 + sum0;
        l1 = l1 * c1 + sum1;
        m0 = m0n; m1 = m1n;
#pragma unroll
        for (int nto = 0; nto < 8; nto++) {
            acc_o[nto][0] *= c0; acc_o[nto][1] *= c0;
            acc_o[nto][2] *= c1; acc_o[nto][3] *= c1;
        }
#pragma unroll
        for (int ks = 0; ks < 8; ks++) {
            unsigned ap[4] = {p[2 * ks][0], p[2 * ks][1], p[2 * ks + 1][0], p[2 * ks + 1][1]};
#pragma unroll
            for (int nto = 0; nto < 8; nto++) {
                unsigned bv[2];
                bv[0] = *(const unsigned*)&VTs[buf][nto * 8 + g][ks * 16 + q * 2];
                bv[1] = *(const unsigned*)&VTs[buf][nto * 8 + g][ks * 16 + q * 2 + 8];
                mma16816(acc_o[nto], ap, bv);
            }
        }
        __syncthreads();
    }

    float i0 = 1.f / l0, i1 = 1.f / l1;
    int row0 = rb * 128 + qrow + g, row1 = row0 + 8;
#pragma unroll
    for (int nto = 0; nto < 8; nto++) {
        int col = h * 64 + nto * 8 + q * 2;
        *(unsigned*)(outp + (size_t)row0 * 512 + col) = packbf(acc_o[nto][0] * i0, acc_o[nto][1] * i0);
        *(unsigned*)(outp + (size_t)row1 * 512 + col) = packbf(acc_o[nto][2] * i1, acc_o[nto][3] * i1);
    }
}

// ---------------------------------------------------------------------------
// Generic bf16 GEMM with 2-level z batching + optional aux relu-bf16 output
// ---------------------------------------------------------------------------
template <int BM, int BN, int WRM, int WRN>
__global__ void __launch_bounds__(256) gemm_bf16(
    int M, int N, int K,
    const bf16* __restrict__ A, int lda,
    const bf16* __restrict__ B, int ldb,
    void* __restrict__ Cv, int ldc,
    const float* __restrict__ bias,
    const float* __restrict__ res, int ldr,
    int flags, float alpha, int zmod,
    long long Az1, long long Az2, long long Bz1, long long Bz2,
    long long Cz1, long long Cz2, long long bz2, long long Rz2,
    bf16* __restrict__ aux, long long auxz2) {
    const int WM = BM / WRM, WN = BN / WRN;
    const int MT = WM / 16, NT = WN / 8;
    __shared__ __align__(16) bf16 As[BM][40];
    __shared__ __align__(16) bf16 Bs[BN][40];

    long long z = blockIdx.z;
    long long z1 = z % zmod, z2 = z / zmod;
    A += z1 * Az1 + z2 * Az2;
    B += z1 * Bz1 + z2 * Bz2;
    long long coff = z1 * Cz1 + z2 * Cz2;
    if (bias) bias += z2 * bz2;
    if (res) res += z2 * Rz2;
    if (aux) aux += z2 * auxz2;

    int m0 = blockIdx.y * BM, n0 = blockIdx.x * BN;
    int tid = threadIdx.x, lane = tid & 31, wid = tid >> 5;
    int g = lane >> 2, q = lane & 3;
    int wm0 = (wid % WRM) * WM, wn0 = (wid / WRM) * WN;

    float acc[MT][NT][4] = {};

    for (int k0 = 0; k0 < K; k0 += 32) {
        __syncthreads();
#pragma unroll
        for (int r = 0; r < BM * 4 / 256; r++) {
            int idx = tid + r * 256;
            int row = idx >> 2, quad = idx & 3;
            uint4 v = *(const uint4*)(A + (size_t)(m0 + row) * lda + k0 + quad * 8);
            *(uint4*)&As[row][quad * 8] = v;
        }
#pragma unroll
        for (int r = 0; r < BN * 4 / 256; r++) {
            int idx = tid + r * 256;
            int row = idx >> 2, quad = idx & 3;
            uint4 v = *(const uint4*)(B + (size_t)(n0 + row) * ldb + k0 + quad * 8);
            *(uint4*)&Bs[row][quad * 8] = v;
        }
        __syncthreads();
#pragma unroll
        for (int kk = 0; kk < 2; kk++) {
            unsigned af[MT][4], bfr[NT][2];
#pragma unroll
            for (int mt = 0; mt < MT; mt++) {
                int row = wm0 + mt * 16 + g;
                af[mt][0] = *(const unsigned*)&As[row][kk * 16 + q * 2];
                af[mt][1] = *(const unsigned*)&As[row + 8][kk * 16 + q * 2];
                af[mt][2] = *(const unsigned*)&As[row][kk * 16 + q * 2 + 8];
                af[mt][3] = *(const unsigned*)&As[row + 8][kk * 16 + q * 2 + 8];
            }
#pragma unroll
            for (int nt = 0; nt < NT; nt++) {
                int col = wn0 + nt * 8 + g;
                bfr[nt][0] = *(const unsigned*)&Bs[col][kk * 16 + q * 2];
                bfr[nt][1] = *(const unsigned*)&Bs[col][kk * 16 + q * 2 + 8];
            }
#pragma unroll
            for (int mt = 0; mt < MT; mt++)
#pragma unroll
                for (int nt = 0; nt < NT; nt++) mma16816(acc[mt][nt], af[mt], bfr[nt]);
        }
    }

    float* Cf = (float*)Cv + coff;
    bf16* Ch = (bf16*)Cv + coff;
#pragma unroll
    for (int mt = 0; mt < MT; mt++) {
#pragma unroll
        for (int nt = 0; nt < NT; nt++) {
#pragma unroll
            for (int e = 0; e < 4; e++) {
                int row = m0 + wm0 + mt * 16 + g + (e >> 1) * 8;
                int col = n0 + wn0 + nt * 8 + q * 2 + (e & 1);
                float v = acc[mt][nt][e] * alpha;
                if (flags & EF_RES)  v += res[(size_t)row * ldr + col];
                if (flags & EF_BIAS) v += bias[col];
                if (flags & EF_RELU) v = fmaxf(v, 0.f);
                if (flags & EF_GELU) v = 0.5f * v * (1.f + erff(v * 0.70710678118654752f));
                if (flags & EF_F16OUT) Ch[(size_t)row * ldc + col] = __float2bfloat16(v);
                else                   Cf[(size_t)row * ldc + col] = v;
                if (flags & EF_AUX)
                    aux[(size_t)row * 512 + col] = __float2bfloat16(fmaxf(v, 0.f));
            }
        }
    }
}

// ---------------------------------------------------------------------------
// fp32 GEMM (head only)
// ---------------------------------------------------------------------------
__global__ void __launch_bounds__(256) gemm_nn(
    int M, int N, int K,
    const float* __restrict__ A, int lda,
    const float* __restrict__ B, int ldb,
    float* __restrict__ C, int ldc,
    const float* __restrict__ bias, int flags) {
    __shared__ __align__(16) float As[16][68];
    __shared__ __align__(16) float Bs[16][68];
    int n0 = blockIdx.x * 64, m0 = blockIdx.y * 64;
    int tid = threadIdx.x, tx = tid & 15, ty = tid >> 4;
    int arow = tid >> 2, akg = tid & 3;
    int brow = tid >> 4, bcg = tid & 15;
    float acc[4][4] = {};
    for (int k0 = 0; k0 < K; k0 += 16) {
        float4 av = *(const float4*)(A + (size_t)(m0 + arow) * lda + k0 + 4 * akg);
        float4 bv = *(const float4*)(B + (size_t)(k0 + brow) * ldb + n0 + 4 * bcg);
        __syncthreads();
        As[4 * akg + 0][arow] = av.x; As[4 * akg + 1][arow] = av.y;
        As[4 * akg + 2][arow] = av.z; As[4 * akg + 3][arow] = av.w;
        *(float4*)&Bs[brow][4 * bcg] = bv;
        __syncthreads();
#pragma unroll
        for (int kk = 0; kk < 16; kk++) {
            float4 a = *(const float4*)&As[kk][ty * 4];
            float4 b = *(const float4*)&Bs[kk][tx * 4];
            acc[0][0] += a.x * b.x; acc[0][1] += a.x * b.y;
            acc[0][2] += a.x * b.z; acc[0][3] += a.x * b.w;
            acc[1][0] += a.y * b.x; acc[1][1] += a.y * b.y;
            acc[1][2] += a.y * b.z; acc[1][3] += a.y * b.w;
            acc[2][0] += a.z * b.x; acc[2][1] += a.z * b.y;
            acc[2][2] += a.z * b.z; acc[2][3] += a.z * b.w;
            acc[3][0] += a.w * b.x; acc[3][1] += a.w * b.y;
            acc[3][2] += a.w * b.z; acc[3][3] += a.w * b.w;
        }
    }
#pragma unroll
    for (int mi = 0; mi < 4; mi++) {
        int row = m0 + ty * 4 + mi;
#pragma unroll
        for (int ni = 0; ni < 4; ni++) {
            int col = n0 + tx * 4 + ni;
            float v = acc[mi][ni];
            if (flags & EF_BIAS) v += bias[col];
            if (flags & EF_RELU) v = fmaxf(v, 0.f);
            C[(size_t)row * ldc + col] = v;
        }
    }
}

// ---------------------------------------------------------------------------
// (x += pos?); out = LN(x)*g + b -> bf16.   grid (1024, 2), block 256
// ---------------------------------------------------------------------------
__global__ void addpos_ln(float* __restrict__ x, const float* __restrict__ pos,
                          const float* __restrict__ g, const float* __restrict__ b,
                          bf16* __restrict__ out) {
    size_t rg = (size_t)blockIdx.y * 1024 + blockIdx.x;
    int br = blockIdx.y, t = threadIdx.x;
    float v = x[rg * 256 + t];
    if (pos) {
        v += pos[rg * 256 + t];
        x[rg * 256 + t] = v;
    }
    float mean = blockReduceSum(v) * (1.f / 256.f);
    float d = v - mean;
    float var = blockReduceSum(d * d) * (1.f / 256.f);
    out[rg * 256 + t] = __float2bfloat16(d * rsqrtf(var + 1e-5f) * g[br * 256 + t] + b[br * 256 + t]);
}

__global__ void absdiff(const float* __restrict__ a, const float* __restrict__ b,
                        float* __restrict__ o) {
    int i = blockIdx.x * 256 + threadIdx.x;
    o[i] = fabsf(a[i] - b[i]);
}

__global__ void head2k(const float* __restrict__ hd, const float* __restrict__ W2,
                       const float* __restrict__ b2, float* __restrict__ out) {
    int row = blockIdx.x, t = threadIdx.x;
    float v = hd[row * 128 + t];
    float l0 = v * W2[2 * t], l1 = v * W2[2 * t + 1];
    __shared__ float s0[4], s1[4];
    int lane = t & 31, w = t >> 5;
#pragma unroll
    for (int o = 16; o; o >>= 1) {
        l0 += __shfl_xor_sync(0xffffffffu, l0, o);
        l1 += __shfl_xor_sync(0xffffffffu, l1, o);
    }
    if (lane == 0) { s0[w] = l0; s1[w] = l1; }
    __syncthreads();
    if (t == 0) {
        float a = s0[0] + s0[1] + s0[2] + s0[3] + b2[0];
        float c = s1[0] + s1[1] + s1[2] + s1[3] + b2[1];
        float m = fmaxf(a, c);
        float e0 = expf(a - m), e1 = expf(c - m);
        float inv = 1.f / (e0 + e1);
        out[row * 2 + 0] = e0 * inv;
        out[row * 2 + 1] = e1 * inv;
    }
}

// ---------------------------------------------------------------------------
// Host orchestration: two-stream fork-join, record-before-wait issue order
// ---------------------------------------------------------------------------
extern "C" void kernel_launch(void* const* d_in, const int* in_sizes, int n_in,
                              void* d_out, int out_size) {
    const float* T[2]     = {(const float*)d_in[0], (const float*)d_in[1]};
    const float* Q        = (const float*)d_in[2];
    const float* Am       = (const float*)d_in[3];
    const float* convW_in = (const float*)d_in[4];
    const float* convB_in = (const float*)d_in[5];
    const float* convW    = (const float*)d_in[6];
    const float* convB    = (const float*)d_in[7];
    const float* fc0_b    = (const float*)d_in[9];
    const float* fc_b     = (const float*)d_in[11];
    const float* pos      = (const float*)d_in[12];
    const float* ln1_g    = (const float*)d_in[13];
    const float* ln1_b    = (const float*)d_in[14];
    const float* out_b    = (const float*)d_in[17];
    const float* ln2_g    = (const float*)d_in[18];
    const float* ln2_b    = (const float*)d_in[19];
    const float* ff_b1    = (const float*)d_in[21];
    const float* ff_b2    = (const float*)d_in[23];
    const float* head_W1  = (const float*)d_in[24];
    const float* head_b1  = (const float*)d_in[25];
    const float* head_W2  = (const float*)d_in[26];
    const float* head_b2  = (const float*)d_in[27];
    float* outp = (float*)d_out;

    void* p;
    cudaGetSymbolAddress(&p, g_convb);  bf16* convb = (bf16*)p;
    cudaGetSymbolAddress(&p, g_tb);     bf16* tb = (bf16*)p;
    cudaGetSymbolAddress(&p, g_wb0);    bf16* wb0 = (bf16*)p;
    cudaGetSymbolAddress(&p, g_wbN);    bf16* wbN = (bf16*)p;
    cudaGetSymbolAddress(&p, g_wenc);   bf16* wenc = (bf16*)p;
    cudaGetSymbolAddress(&p, g_amb);    bf16* amb = (bf16*)p;
    cudaGetSymbolAddress(&p, g_catb);   bf16* catb = (bf16*)p;
    cudaGetSymbolAddress(&p, g_hb);     bf16* hb = (bf16*)p;
    cudaGetSymbolAddress(&p, g_qkvb);   bf16* qkvb = (bf16*)p;
    cudaGetSymbolAddress(&p, g_vT);     bf16* vT = (bf16*)p;
    cudaGetSymbolAddress(&p, g_attnob); bf16* attnob = (bf16*)p;
    cudaGetSymbolAddress(&p, g_ff1b);   bf16* ff1b = (bf16*)p;
    cudaGetSymbolAddress(&p, g_x);      float* x = (float*)p;
    cudaGetSymbolAddress(&p, g_dd);     float* dd = (float*)p;
    cudaGetSymbolAddress(&p, g_hd);     float* hd = (float*)p;

    cudaFuncSetAttribute(conv_mma<224>, cudaFuncAttributeMaxDynamicSharedMemorySize, CONV_SMEM);
    cudaFuncSetAttribute(conv_mma<256>, cudaFuncAttributeMaxDynamicSharedMemorySize, CONV_SMEM);
    cudaFuncSetAttribute(fused_attn, cudaFuncAttributeMaxDynamicSharedMemorySize, FA_SMEM);

    // one-time host-side resources (no device memory)
    static cudaStream_t s1 = nullptr;
    static cudaEvent_t evFork, evConv[NSTG], evCt[NSTG];
    if (!s1) {
        cudaStreamCreateWithFlags(&s1, cudaStreamNonBlocking);
        cudaEventCreateWithFlags(&evFork, cudaEventDisableTiming);
        for (int i = 0; i < NSTG; i++) {
            cudaEventCreateWithFlags(&evConv[i], cudaEventDisableTiming);
            cudaEventCreateWithFlags(&evCt[i], cudaEventDisableTiming);
        }
    }

    const long long PP = 4194304;

    // ---- fork ----
    cudaEventRecord(evFork, 0);
    cudaStreamWaitEvent(s1, evFork, 0);

    // ---- conv chain prolog + conv0, conv1 ----
    chw2hwc<<<dim3(512, 7), dim3(32, 8), 0, s1>>>(T[0], tb, 224);
    chw2hwc<<<dim3(512, 7), dim3(32, 8), 0, s1>>>(T[1], tb + 16384ll * 224, 224);
    repack_w<224><<<4032, 256, 0, s1>>>(convW_in, wb0);
    conv_mma<224><<<dim3(64, 2, 2), 256, CONV_SMEM, s1>>>(
        tb, wb0, convB_in, convb, 16384ll * 224, 9ll * 256 * 224, 2 * PP);
    cudaEventRecord(evConv[0], s1);
    repack_w<256><<<23040, 256, 0, s1>>>(convW, wbN);
    conv_mma<256><<<dim3(64, 2, 2), 256, CONV_SMEM, s1>>>(
        convb, wbN, convB, convb + PP, 2 * PP, 9ll * 256 * 256, 2 * PP);
    cudaEventRecord(evConv[1], s1);

    // ---- encoder prolog (main stream) ----
    build_sp<<<1024, 256>>>(Q);
    f32_to_bf16<<<4096, 256>>>(Am, amb);
    wconv_t<<<dim3(48, 8, 12), dim3(32, 8)>>>((const float*)d_in[15], wenc + OFF_QKV, 256, 1536);
    wconv_t<<<dim3(8, 16, 12), dim3(32, 8)>>>((const float*)d_in[16], wenc + OFF_O, 512, 256);
    wconv_t<<<dim3(16, 8, 12), dim3(32, 8)>>>((const float*)d_in[20], wenc + OFF_W1, 256, 512);
    wconv_t<<<dim3(8, 16, 12), dim3(32, 8)>>>((const float*)d_in[22], wenc + OFF_W2, 512, 256);
    wconv_t<<<dim3(8, 15, 2), dim3(32, 8)>>>((const float*)d_in[8], wenc + OFF_FC0, 480, 256);
    wconv_t<<<dim3(8, 16, 10), dim3(32, 8)>>>((const float*)d_in[10], wenc + OFF_FC, 512, 256);
    ct_mean_f32<<<dim3(224, 4), 256>>>(T[0], catb, 256);
    ct_mean_f32<<<dim3(224, 4), 256>>>(T[1], catb + 524288, 256);

    for (int s = 0; s < NSTG; s++) {
        int sbase = s * 2;
        cudaStreamWaitEvent(0, evConv[s], 0);
        ct_nhwc<<<dim3(1024, 2), 256>>>(convb + (s & 1) * PP, 2 * PP, catb, 524288);
        cudaEventRecord(evCt[s], 0);
        if (s + 2 < NSTG) {
            int cw = (s + 1) * 2;
            cudaStreamWaitEvent(s1, evCt[s], 0);
            conv_mma<256><<<dim3(64, 2, 2), 256, CONV_SMEM, s1>>>(
                convb + ((s + 1) & 1) * PP, wbN + (size_t)cw * 9 * 256 * 256,
                convB + cw * 256, convb + (s & 1) * PP, 2 * PP, 9ll * 256 * 256, 2 * PP);
            cudaEventRecord(evConv[s + 2], s1);
        }
        if (s == 0) {
            gemm_bf16<64, 64, 2, 4><<<dim3(4, 16, 2), 256>>>(
                1024, 256, 480, catb, 512, wenc + OFF_FC0, 480, x, 256,
                fc0_b, nullptr, 0, EF_BIAS, 1.f, 1,
                0, 524288, 0, 122880, 0, 262144, 256, 0, nullptr, 0);
        } else {
            int cw = (s - 1) * 2;
            gemm_bf16<64, 64, 2, 4><<<dim3(4, 16, 2), 256>>>(
                1024, 256, 512, catb, 512, wenc + OFF_FC + (size_t)cw * 131072, 512, x, 256,
                fc_b + cw * 256, nullptr, 0, EF_BIAS, 1.f, 1,
                0, 524288, 0, 131072, 0, 262144, 256, 0, nullptr, 0);
        }
        addpos_ln<<<dim3(1024, 2), 256>>>(x, pos + (size_t)sbase * 262144,
                                          ln1_g + sbase * 256, ln1_b + sbase * 256, hb);
        gemm_bf16<128, 128, 2, 4><<<dim3(12, 8, 2), 256>>>(
            1024, 1536, 256, hb, 256, wenc + OFF_QKV + (size_t)sbase * 393216, 256,
            qkvb, 1536, nullptr, nullptr, 0, EF_F16OUT, 1.f, 1,
            0, 262144, 0, 393216, 0, 1572864, 0, 0, nullptr, 0);
        transpose_v<<<dim3(16, 32, 2), dim3(32, 8)>>>(qkvb, vT);
        fused_attn<<<dim3(8, 8, 2), 256, FA_SMEM>>>(qkvb, vT, amb, attnob);
        gemm_bf16<64, 64, 2, 4><<<dim3(4, 16, 2), 256>>>(
            1024, 256, 512, attnob, 512, wenc + OFF_O + (size_t)sbase * 131072, 512, x, 256,
            out_b + sbase * 256, x, 256, EF_BIAS | EF_RES, 1.f, 1,
            0, 524288, 0, 131072, 0, 262144, 256, 262144, nullptr, 0);
        addpos_ln<<<dim3(1024, 2), 256>>>(x, nullptr,
                                          ln2_g + sbase * 256, ln2_b + sbase * 256, hb);
        gemm_bf16<64, 64, 2, 4><<<dim3(8, 16, 2), 256>>>(
            1024, 512, 256, hb, 256, wenc + OFF_W1 + (size_t)sbase * 131072, 256,
            ff1b, 512, ff_b1 + sbase * 512, nullptr, 0,
            EF_BIAS | EF_GELU | EF_F16OUT, 1.f, 1,
            0, 262144, 0, 131072, 0, 524288, 512, 0, nullptr, 0);
        gemm_bf16<64, 64, 2, 4><<<dim3(4, 16, 2), 256>>>(
            1024, 256, 512, ff1b, 512, wenc + OFF_W2 + (size_t)sbase * 131072, 512, x, 256,
            ff_b2 + sbase * 256, x, 256, EF_BIAS | EF_RES | EF_AUX, 1.f, 1,
            0, 524288, 0, 131072, 0, 262144, 256, 262144, catb + 256, 524288);
    }

    // ---- head ----
    absdiff<<<1024, 256>>>(x, x + 262144, dd);
    gemm_nn<<<dim3(2, 16), 256>>>(1024, 128, 256, dd, 256, head_W1, 128,
                                  hd, 128, head_b1, EF_BIAS | EF_RELU);
    head2k<<<1024, 128>>>(hd, head_W2, head_b2, outp);
}

// round 16
// speedup vs baseline: 1.0302x; 1.0001x over previous
#include <cuda_runtime.h>
#include <cuda_bf16.h>
#include <cuda_fp16.h>
#include <math.h>

#define SPX   1024
#define HWPX  16384
#define IMW   128
#define NSTG  6

#define EF_BIAS   1
#define EF_RELU   2
#define EF_GELU   4
#define EF_RES    8
#define EF_F16OUT 16
#define EF_AUX    32

typedef __nv_bfloat16 bf16;

// ---------------------------------------------------------------------------
// Scratch
// ---------------------------------------------------------------------------
__device__ bf16  g_convb[4ull * 16384 * 256];    // NHWC activations [slab*2+br]
__device__ bf16  g_tb[2ull * 16384 * 224];       // NHWC bf16 copies of T1/T2
__device__ bf16  g_wb0[2ull * 9 * 256 * 224];    // stage-0 conv weights
__device__ bf16  g_wbN[10ull * 9 * 256 * 256];   // stage-1..5 conv weights
__device__ bf16  g_wenc[11000832];               // transposed encoder/fc weights
__device__ bf16  g_amb[1024 * 1024];             // bf16 copy of attention bias A
__device__ bf16  g_catb[2ull * 1024 * 512];
__device__ bf16  g_hb[2ull * 1024 * 256];
__device__ bf16  g_qkvb[2ull * 1024 * 1536];
__device__ bf16  g_vT[2ull * 512 * 1024];
__device__ bf16  g_attnob[2ull * 1024 * 512];
__device__ bf16  g_ff1b[2ull * 1024 * 512];
__device__ float g_x[2ull * 1024 * 256];
__device__ float g_dd[1024 * 256];
__device__ float g_hd[1024 * 128];
__device__ int   g_splist[1024 * 64];
__device__ int   g_spcnt[1024];

#define OFF_QKV 0
#define OFF_O   4718592
#define OFF_W1  6291456
#define OFF_W2  7864320
#define OFF_FC0 9437184
#define OFF_FC  9682944

// ---------------------------------------------------------------------------
// cp.async helpers
// ---------------------------------------------------------------------------
#define CPA16(dst, src) \
    asm volatile("cp.async.cg.shared.global [%0], [%1], 16;\n" ::"r"(dst), "l"(src))
#define CPA_COMMIT asm volatile("cp.async.commit_group;\n")
#define CPA_WAIT0  asm volatile("cp.async.wait_group 0;\n")
#define CPA_WAIT1  asm volatile("cp.async.wait_group 1;\n")

// ---------------------------------------------------------------------------
// Block reductions
// ---------------------------------------------------------------------------
__device__ __forceinline__ float blockReduceSum(float v) {
    __shared__ float sh[8];
    int lane = threadIdx.x & 31, w = threadIdx.x >> 5;
#pragma unroll
    for (int o = 16; o; o >>= 1) v += __shfl_xor_sync(0xffffffffu, v, o);
    if (lane == 0) sh[w] = v;
    __syncthreads();
    float r = (threadIdx.x < 8) ? sh[threadIdx.x] : 0.f;
    if (w == 0) {
#pragma unroll
        for (int o = 4; o; o >>= 1) r += __shfl_xor_sync(0xffffffffu, r, o);
        if (lane == 0) sh[0] = r;
    }
    __syncthreads();
    float out = sh[0];
    __syncthreads();
    return out;
}

// ---------------------------------------------------------------------------
// Superpixel list builder
// ---------------------------------------------------------------------------
__global__ void build_sp(const float* __restrict__ Q) {
    int s = blockIdx.x;
    __shared__ int wcnt[8];
    __shared__ int cnt;
    if (threadIdx.x == 0) cnt = 0;
    __syncthreads();
    int lane = threadIdx.x & 31, warp = threadIdx.x >> 5;
    for (int base = 0; base < HWPX; base += 256) {
        int p = base + threadIdx.x;
        bool m = Q[(size_t)p * SPX + s] > 0.5f;
        unsigned bal = __ballot_sync(0xffffffffu, m);
        if (lane == 0) wcnt[warp] = __popc(bal);
        __syncthreads();
        int off = cnt;
        for (int w = 0; w < warp; w++) off += wcnt[w];
        off += __popc(bal & ((1u << lane) - 1u));
        if (m && off < 64) g_splist[s * 64 + off] = p;
        __syncthreads();
        if (threadIdx.x == 0) {
            int t = 0;
            for (int w = 0; w < 8; w++) t += wcnt[w];
            cnt += t;
        }
        __syncthreads();
    }
    if (threadIdx.x == 0) g_spcnt[s] = cnt < 64 ? cnt : 64;
}

// ---------------------------------------------------------------------------
// ct pooling (MLP-16 fast path; identical ascending add order)
// ---------------------------------------------------------------------------
__global__ void ct_nhwc(const bf16* __restrict__ img, long long imgz,
                        bf16* __restrict__ out, long long outz) {
    int s = blockIdx.x, c = threadIdx.x;
    img += (size_t)blockIdx.y * imgz;
    out += (size_t)blockIdx.y * outz;
    int cnt = g_spcnt[s];
    const int* lst = &g_splist[s * 64];
    float sum = 0.f;
    if (cnt == 16) {
        int idxs[16];
#pragma unroll
        for (int i = 0; i < 16; i++) idxs[i] = lst[i];
        float v[16];
#pragma unroll
        for (int i = 0; i < 16; i++)
            v[i] = __bfloat162float(img[(size_t)idxs[i] * 256 + c]);
#pragma unroll
        for (int i = 0; i < 16; i++) sum += v[i];
    } else {
        for (int i = 0; i < cnt; i++)
            sum += __bfloat162float(img[(size_t)lst[i] * 256 + c]);
    }
    out[(size_t)s * 512 + c] = __float2bfloat16(fmaxf(sum / (float)cnt, 0.f));
}

__global__ void ct_mean_f32(const float* __restrict__ img, bf16* __restrict__ out,
                            int coloff) {
    int c = blockIdx.x;
    int s = blockIdx.y * 256 + threadIdx.x;
    int cnt = g_spcnt[s];
    const int* lst = &g_splist[s * 64];
    float sum = 0.f;
    for (int i = 0; i < cnt; i++) sum += img[(size_t)c * HWPX + lst[i]];
    out[(size_t)s * 512 + coloff + c] = __float2bfloat16(fmaxf(sum / (float)cnt, 0.f));
}

// NCHW fp32 -> NHWC bf16 transpose. grid (512, 7), block (32,8).
__global__ void chw2hwc(const float* __restrict__ in, bf16* __restrict__ out, int C) {
    __shared__ float sm[32][33];
    int p0 = blockIdx.x * 32, c0 = blockIdx.y * 32;
    int tx = threadIdx.x, ty = threadIdx.y;
#pragma unroll
    for (int j = 0; j < 4; j++)
        sm[ty + 8 * j][tx] = in[(size_t)(c0 + ty + 8 * j) * HWPX + p0 + tx];
    __syncthreads();
#pragma unroll
    for (int j = 0; j < 4; j++)
        out[(size_t)(p0 + ty + 8 * j) * C + c0 + tx] = __float2bfloat16(sm[tx][ty + 8 * j]);
}

__global__ void f32_to_bf16(const float* __restrict__ in, bf16* __restrict__ out) {
    int i = blockIdx.x * 256 + threadIdx.x;
    out[i] = __float2bfloat16(in[i]);
}

// conv weight repack: [z][oc][ic][3][3] f32 -> [z][tap][oc][ic] bf16
template <int CIN>
__global__ void repack_w(const float* __restrict__ W, bf16* __restrict__ out) {
    int idx = blockIdx.x * 256 + threadIdx.x;
    int t = idx / (256 * CIN);
    int z = t / 9, tap = t % 9;
    int rem = idx - t * 256 * CIN;
    int oc = rem / CIN;
    int ic = rem - oc * CIN;
    out[idx] = __float2bfloat16(W[(size_t)z * 9 * 256 * CIN + ((size_t)oc * CIN + ic) * 9 + tap]);
}

// batched transpose+convert: in [Z][K][N] f32 -> out [Z][N][K] bf16
__global__ void wconv_t(const float* __restrict__ in, bf16* __restrict__ out,
                        int K, int N) {
    __shared__ float sm[32][33];
    int n0 = blockIdx.x * 32, k0 = blockIdx.y * 32;
    const float* inz = in + (size_t)blockIdx.z * K * N;
    bf16* outz = out + (size_t)blockIdx.z * K * N;
    int tx = threadIdx.x, ty = threadIdx.y;
#pragma unroll
    for (int j = 0; j < 4; j++)
        sm[ty + 8 * j][tx] = inz[(size_t)(k0 + ty + 8 * j) * N + n0 + tx];
    __syncthreads();
#pragma unroll
    for (int j = 0; j < 4; j++)
        outz[(size_t)(n0 + ty + 8 * j) * K + k0 + tx] = __float2bfloat16(sm[tx][ty + 8 * j]);
}

// transpose V slice of qkv -> vT.  grid (16, 32, 2), block (32, 8).
__global__ void transpose_v(const bf16* __restrict__ qkv, bf16* __restrict__ vT) {
    __shared__ bf16 sm[32][33];
    qkv += (size_t)blockIdx.z * 1024 * 1536;
    vT += (size_t)blockIdx.z * 512 * 1024;
    int c0 = blockIdx.x * 32, m0 = blockIdx.y * 32;
    int tx = threadIdx.x, ty = threadIdx.y;
#pragma unroll
    for (int j = 0; j < 4; j++)
        sm[ty + 8 * j][tx] = qkv[(size_t)(m0 + ty + 8 * j) * 1536 + 1024 + c0 + tx];
    __syncthreads();
#pragma unroll
    for (int j = 0; j < 4; j++)
        vT[(size_t)(c0 + ty + 8 * j) * 1024 + m0 + tx] = sm[tx][ty + 8 * j];
}

// ---------------------------------------------------------------------------
// mma helpers
// ---------------------------------------------------------------------------
__device__ __forceinline__ void mma16816(float* c, const unsigned* a, const unsigned* b) {
    asm volatile(
        "mma.sync.aligned.m16n8k16.row.col.f32.bf16.bf16.f32 "
        "{%0,%1,%2,%3}, {%4,%5,%6,%7}, {%8,%9}, {%0,%1,%2,%3};\n"
        : "+f"(c[0]), "+f"(c[1]), "+f"(c[2]), "+f"(c[3])
        : "r"(a[0]), "r"(a[1]), "r"(a[2]), "r"(a[3]), "r"(b[0]), "r"(b[1]));
}

__device__ __forceinline__ unsigned packbf(float a, float b) {
    __nv_bfloat162 t = __floats2bfloat162_rn(a, b);
    return *(unsigned*)&t;
}

// ---------------------------------------------------------------------------
// Tensor-core 3x3 SAME conv, NHWC bf16 (R12-proven: 2 rows x 128 oc, occ 1)
// ---------------------------------------------------------------------------
#define CONV_SMEM 161280

template <int CIN>
__global__ void __launch_bounds__(256, 1) conv_mma(
    const bf16* __restrict__ X, const bf16* __restrict__ Wb,
    const float* __restrict__ Bias, bf16* __restrict__ Y,
    long long Xz, long long Wz, long long Yz) {
    extern __shared__ char smem[];
    bf16 (*stageX)[4][132][24] = (bf16(*)[4][132][24])(smem);
    bf16 (*Wt)[9][128][24]     = (bf16(*)[9][128][24])(smem + 50688);
    bf16 (*stageO)[136]        = (bf16(*)[136])(smem);

    int y0 = blockIdx.x * 2;
    int ochalf = blockIdx.y;
    X += (size_t)blockIdx.z * Xz;
    Wb += (size_t)blockIdx.z * Wz;
    Bias += (size_t)blockIdx.z * 256;
    Y += (size_t)blockIdx.z * Yz;

    int tid = threadIdx.x;
    int lane = tid & 31, wid = tid >> 5;
    int g = lane >> 2, q = lane & 3;
    int mw = wid & 3, nw = wid >> 2;
    int mrow = mw >> 1, mx0 = (mw & 1) * 64;

    const int CH = CIN / 16;
    float acc[4][8][4] = {};

    auto load_chunk = [&](int buf, int ch) {
        int ic0 = ch * 16;
        for (int idx = tid; idx < 1056; idx += 256) {
            int r = idx / 264, rem = idx % 264;
            int pxi = rem >> 1, half = rem & 1;
            int gy = y0 + r - 1, gx = pxi - 1;
            bf16* dst = &stageX[buf][r][pxi][half * 8];
            if (gy >= 0 && gy < 128 && gx >= 0 && gx < 128) {
                const bf16* src = X + ((size_t)gy * IMW + gx) * CIN + ic0 + half * 8;
                CPA16((unsigned)__cvta_generic_to_shared(dst), src);
            } else {
                *(uint4*)dst = make_uint4(0u, 0u, 0u, 0u);
            }
        }
        for (int idx = tid; idx < 2304; idx += 256) {
            int tap = idx / 256, rem = idx % 256;
            int oc = rem >> 1, half = rem & 1;
            bf16* dst = &Wt[buf][tap][oc][half * 8];
            const bf16* src = Wb + ((size_t)tap * 256 + ochalf * 128 + oc) * CIN + ic0 + half * 8;
            CPA16((unsigned)__cvta_generic_to_shared(dst), src);
        }
        CPA_COMMIT;
    };

    load_chunk(0, 0);
    int buf = 0;
    for (int ch = 0; ch < CH; ch++) {
        CPA_WAIT0;
        __syncthreads();
        if (ch + 1 < CH) load_chunk(buf ^ 1, ch + 1);
#pragma unroll
        for (int tap = 0; tap < 9; tap++) {
            int ky = tap / 3, kx = tap % 3;
            unsigned bfr[8][2];
#pragma unroll
            for (int nt = 0; nt < 8; nt++) {
                int oc = nw * 64 + nt * 8 + g;
                bfr[nt][0] = *(const unsigned*)&Wt[buf][tap][oc][q * 2];
                bfr[nt][1] = *(const unsigned*)&Wt[buf][tap][oc][q * 2 + 8];
            }
#pragma unroll
            for (int mt = 0; mt < 4; mt++) {
                int p0 = mx0 + mt * 16 + kx;
                unsigned af[4];
                af[0] = *(const unsigned*)&stageX[buf][mrow + ky][p0 + g][q * 2];
                af[1] = *(const unsigned*)&stageX[buf][mrow + ky][p0 + g + 8][q * 2];
                af[2] = *(const unsigned*)&stageX[buf][mrow + ky][p0 + g][q * 2 + 8];
                af[3] = *(const unsigned*)&stageX[buf][mrow + ky][p0 + g + 8][q * 2 + 8];
#pragma unroll
                for (int nt = 0; nt < 8; nt++) mma16816(acc[mt][nt], af, bfr[nt]);
            }
        }
        buf ^= 1;
    }

    __syncthreads();
#pragma unroll
    for (int mt = 0; mt < 4; mt++) {
#pragma unroll
        for (int nt = 0; nt < 8; nt++) {
            int m = mrow * 128 + mx0 + mt * 16 + g;
            int n = nw * 64 + nt * 8 + q * 2;
            float b0 = Bias[ochalf * 128 + n];
            float b1 = Bias[ochalf * 128 + n + 1];
            stageO[m][n]         = __float2bfloat16(acc[mt][nt][0] + b0);
            stageO[m][n + 1]     = __float2bfloat16(acc[mt][nt][1] + b1);
            stageO[m + 8][n]     = __float2bfloat16(acc[mt][nt][2] + b0);
            stageO[m + 8][n + 1] = __float2bfloat16(acc[mt][nt][3] + b1);
        }
    }
    __syncthreads();
    for (int idx = tid; idx < 4096; idx += 256) {
        int px = idx >> 4, v = idx & 15;
        uint4 val = *(const uint4*)&stageO[px][v * 8];
        *(uint4*)(Y + ((size_t)(y0 + (px >> 7)) * IMW + (px & 127)) * 256
                  + ochalf * 128 + v * 8) = val;
    }
}

// ---------------------------------------------------------------------------
// Fused flash attention; bf16 A bias; probs via ex2.approx.f16x2 (h2exp2)
// ---------------------------------------------------------------------------
#define FA_SMEM 159744
#define FA_KS   18432
#define FA_VT   55296
#define FA_AS   90112
#define L2E     1.44269504088896f

__global__ void __launch_bounds__(256, 1) fused_attn(
    const bf16* __restrict__ qkv, const bf16* __restrict__ vT,
    const bf16* __restrict__ Amb, bf16* __restrict__ outp) {
    extern __shared__ char smem[];
    bf16 (*Qs)[72]        = (bf16(*)[72])(smem);
    bf16 (*Ks)[128][72]   = (bf16(*)[128][72])(smem + FA_KS);
    bf16 (*VTs)[64][136]  = (bf16(*)[64][136])(smem + FA_VT);
    bf16 (*As)[128][136]  = (bf16(*)[128][136])(smem + FA_AS);

    int rb = blockIdx.x, h = blockIdx.y, br = blockIdx.z;
    qkv += (size_t)br * 1024 * 1536;
    vT += (size_t)br * 512 * 1024;
    outp += (size_t)br * 1024 * 512;

    int tid = threadIdx.x;
    int lane = tid & 31, wid = tid >> 5;
    int g = lane >> 2, q = lane & 3;
    int qrow = wid * 16;

    auto load_j = [&](int buf, int j) {
        int kbase = j * 128;
        for (int idx = tid; idx < 1024; idx += 256) {
            int r = idx >> 3, c = idx & 7;
            CPA16((unsigned)__cvta_generic_to_shared(&Ks[buf][r][c * 8]),
                  qkv + (size_t)(kbase + r) * 1536 + 512 + h * 64 + c * 8);
        }
        for (int idx = tid; idx < 1024; idx += 256) {
            int r = idx >> 4, c = idx & 15;
            CPA16((unsigned)__cvta_generic_to_shared(&VTs[buf][r][c * 8]),
                  vT + (size_t)(h * 64 + r) * 1024 + kbase + c * 8);
        }
        for (int idx = tid; idx < 2048; idx += 256) {
            int r = idx >> 4, c = idx & 15;
            CPA16((unsigned)__cvta_generic_to_shared(&As[buf][r][c * 8]),
                  Amb + (size_t)(rb * 128 + r) * 1024 + kbase + c * 8);
        }
        CPA_COMMIT;
    };

    for (int idx = tid; idx < 1024; idx += 256) {
        int r = idx >> 3, c = idx & 7;
        CPA16((unsigned)__cvta_generic_to_shared(&Qs[r][c * 8]),
              qkv + (size_t)(rb * 128 + r) * 1536 + h * 64 + c * 8);
    }
    load_j(0, 0);

    float m0 = -1e30f, m1 = -1e30f, l0 = 0.f, l1 = 0.f;
    float acc_o[8][4] = {};

    for (int j = 0; j < 8; j++) {
        int buf = j & 1;
        if (j < 7) { load_j(buf ^ 1, j + 1); CPA_WAIT1; }
        else       { CPA_WAIT0; }
        __syncthreads();

        float s[16][4] = {};
#pragma unroll
        for (int ks = 0; ks < 4; ks++) {
            unsigned aq[4];
            aq[0] = *(const unsigned*)&Qs[qrow + g][ks * 16 + q * 2];
            aq[1] = *(const unsigned*)&Qs[qrow + g + 8][ks * 16 + q * 2];
            aq[2] = *(const unsigned*)&Qs[qrow + g][ks * 16 + q * 2 + 8];
            aq[3] = *(const unsigned*)&Qs[qrow + g + 8][ks * 16 + q * 2 + 8];
#pragma unroll
            for (int nt = 0; nt < 16; nt++) {
                unsigned bk[2];
                bk[0] = *(const unsigned*)&Ks[buf][nt * 8 + g][ks * 16 + q * 2];
                bk[1] = *(const unsigned*)&Ks[buf][nt * 8 + g][ks * 16 + q * 2 + 8];
                mma16816(s[nt], aq, bk);
            }
        }
#pragma unroll
        for (int nt = 0; nt < 16; nt++) {
            int col = nt * 8 + q * 2;
            s[nt][0] = s[nt][0] * 0.125f + __bfloat162float(As[buf][qrow + g][col]);
            s[nt][1] = s[nt][1] * 0.125f + __bfloat162float(As[buf][qrow + g][col + 1]);
            s[nt][2] = s[nt][2] * 0.125f + __bfloat162float(As[buf][qrow + g + 8][col]);
            s[nt][3] = s[nt][3] * 0.125f + __bfloat162float(As[buf][qrow + g + 8][col + 1]);
        }
        float mx0 = -1e30f, mx1 = -1e30f;
#pragma unroll
        for (int nt = 0; nt < 16; nt++) {
            mx0 = fmaxf(mx0, fmaxf(s[nt][0], s[nt][1]));
            mx1 = fmaxf(mx1, fmaxf(s[nt][2], s[nt][3]));
        }
#pragma unroll
        for (int o = 1; o <= 2; o <<= 1) {
            mx0 = fmaxf(mx0, __shfl_xor_sync(0xffffffffu, mx0, o));
            mx1 = fmaxf(mx1, __shfl_xor_sync(0xffffffffu, mx1, o));
        }
        float m0n = fmaxf(m0, mx0), m1n = fmaxf(m1, mx1);
        float c0 = exp2f((m0 - m0n) * L2E), c1 = exp2f((m1 - m1n) * L2E);
        float sum0 = 0.f, sum1 = 0.f;
        unsigned p[16][2];
#pragma unroll
        for (int nt = 0; nt < 16; nt++) {
            // probs via f16x2 exp2 (ex2.approx.f16x2): 2 exps per MUFU op.
            __half2 e01 = h2exp2(__floats2half2_rn((s[nt][0] - m0n) * L2E,
                                                   (s[nt][1] - m0n) * L2E));
            __half2 e23 = h2exp2(__floats2half2_rn((s[nt][2] - m1n) * L2E,
                                                   (s[nt][3] - m1n) * L2E));
            float2 f01 = __half22float2(e01);
            float2 f23 = __half22float2(e23);
            sum0 += f01.x + f01.y;
            sum1 += f23.x + f23.y;
            p[nt][0] = packbf(f01.x, f01.y);
            p[nt][1] = packbf(f23.x, f23.y);
        }
#pragma unroll
        for (int o = 1; o <= 2; o <<= 1) {
            sum0 += __shfl_xor_sync(0xffffffffu, sum0, o);
            sum1 += __shfl_xor_sync(0xffffffffu, sum1, o);
        }
        l0 = l0 * c0 + sum0;
        l1 = l1 * c1 + sum1;
        m0 = m0n; m1 = m1n;
#pragma unroll
        for (int nto = 0; nto < 8; nto++) {
            acc_o[nto][0] *= c0; acc_o[nto][1] *= c0;
            acc_o[nto][2] *= c1; acc_o[nto][3] *= c1;
        }
#pragma unroll
        for (int ks = 0; ks < 8; ks++) {
            unsigned ap[4] = {p[2 * ks][0], p[2 * ks][1], p[2 * ks + 1][0], p[2 * ks + 1][1]};
#pragma unroll
            for (int nto = 0; nto < 8; nto++) {
                unsigned bv[2];
                bv[0] = *(const unsigned*)&VTs[buf][nto * 8 + g][ks * 16 + q * 2];
                bv[1] = *(const unsigned*)&VTs[buf][nto * 8 + g][ks * 16 + q * 2 + 8];
                mma16816(acc_o[nto], ap, bv);
            }
        }
        __syncthreads();
    }

    float i0 = 1.f / l0, i1 = 1.f / l1;
    int row0 = rb * 128 + qrow + g, row1 = row0 + 8;
#pragma unroll
    for (int nto = 0; nto < 8; nto++) {
        int col = h * 64 + nto * 8 + q * 2;
        *(unsigned*)(outp + (size_t)row0 * 512 + col) = packbf(acc_o[nto][0] * i0, acc_o[nto][1] * i0);
        *(unsigned*)(outp + (size_t)row1 * 512 + col) = packbf(acc_o[nto][2] * i1, acc_o[nto][3] * i1);
    }
}

// ---------------------------------------------------------------------------
// Generic bf16 GEMM with 2-level z batching + optional aux relu-bf16 output
// ---------------------------------------------------------------------------
template <int BM, int BN, int WRM, int WRN>
__global__ void __launch_bounds__(256) gemm_bf16(
    int M, int N, int K,
    const bf16* __restrict__ A, int lda,
    const bf16* __restrict__ B, int ldb,
    void* __restrict__ Cv, int ldc,
    const float* __restrict__ bias,
    const float* __restrict__ res, int ldr,
    int flags, float alpha, int zmod,
    long long Az1, long long Az2, long long Bz1, long long Bz2,
    long long Cz1, long long Cz2, long long bz2, long long Rz2,
    bf16* __restrict__ aux, long long auxz2) {
    const int WM = BM / WRM, WN = BN / WRN;
    const int MT = WM / 16, NT = WN / 8;
    __shared__ __align__(16) bf16 As[BM][40];
    __shared__ __align__(16) bf16 Bs[BN][40];

    long long z = blockIdx.z;
    long long z1 = z % zmod, z2 = z / zmod;
    A += z1 * Az1 + z2 * Az2;
    B += z1 * Bz1 + z2 * Bz2;
    long long coff = z1 * Cz1 + z2 * Cz2;
    if (bias) bias += z2 * bz2;
    if (res) res += z2 * Rz2;
    if (aux) aux += z2 * auxz2;

    int m0 = blockIdx.y * BM, n0 = blockIdx.x * BN;
    int tid = threadIdx.x, lane = tid & 31, wid = tid >> 5;
    int g = lane >> 2, q = lane & 3;
    int wm0 = (wid % WRM) * WM, wn0 = (wid / WRM) * WN;

    float acc[MT][NT][4] = {};

    for (int k0 = 0; k0 < K; k0 += 32) {
        __syncthreads();
#pragma unroll
        for (int r = 0; r < BM * 4 / 256; r++) {
            int idx = tid + r * 256;
            int row = idx >> 2, quad = idx & 3;
            uint4 v = *(const uint4*)(A + (size_t)(m0 + row) * lda + k0 + quad * 8);
            *(uint4*)&As[row][quad * 8] = v;
        }
#pragma unroll
        for (int r = 0; r < BN * 4 / 256; r++) {
            int idx = tid + r * 256;
            int row = idx >> 2, quad = idx & 3;
            uint4 v = *(const uint4*)(B + (size_t)(n0 + row) * ldb + k0 + quad * 8);
            *(uint4*)&Bs[row][quad * 8] = v;
        }
        __syncthreads();
#pragma unroll
        for (int kk = 0; kk < 2; kk++) {
            unsigned af[MT][4], bfr[NT][2];
#pragma unroll
            for (int mt = 0; mt < MT; mt++) {
                int row = wm0 + mt * 16 + g;
                af[mt][0] = *(const unsigned*)&As[row][kk * 16 + q * 2];
                af[mt][1] = *(const unsigned*)&As[row + 8][kk * 16 + q * 2];
                af[mt][2] = *(const unsigned*)&As[row][kk * 16 + q * 2 + 8];
                af[mt][3] = *(const unsigned*)&As[row + 8][kk * 16 + q * 2 + 8];
            }
#pragma unroll
            for (int nt = 0; nt < NT; nt++) {
                int col = wn0 + nt * 8 + g;
                bfr[nt][0] = *(const unsigned*)&Bs[col][kk * 16 + q * 2];
                bfr[nt][1] = *(const unsigned*)&Bs[col][kk * 16 + q * 2 + 8];
            }
#pragma unroll
            for (int mt = 0; mt < MT; mt++)
#pragma unroll
                for (int nt = 0; nt < NT; nt++) mma16816(acc[mt][nt], af[mt], bfr[nt]);
        }
    }

    float* Cf = (float*)Cv + coff;
    bf16* Ch = (bf16*)Cv + coff;
#pragma unroll
    for (int mt = 0; mt < MT; mt++) {
#pragma unroll
        for (int nt = 0; nt < NT; nt++) {
#pragma unroll
            for (int e = 0; e < 4; e++) {
                int row = m0 + wm0 + mt * 16 + g + (e >> 1) * 8;
                int col = n0 + wn0 + nt * 8 + q * 2 + (e & 1);
                float v = acc[mt][nt][e] * alpha;
                if (flags & EF_RES)  v += res[(size_t)row * ldr + col];
                if (flags & EF_BIAS) v += bias[col];
                if (flags & EF_RELU) v = fmaxf(v, 0.f);
                if (flags & EF_GELU) v = 0.5f * v * (1.f + erff(v * 0.70710678118654752f));
                if (flags & EF_F16OUT) Ch[(size_t)row * ldc + col] = __float2bfloat16(v);
                else                   Cf[(size_t)row * ldc + col] = v;
                if (flags & EF_AUX)
                    aux[(size_t)row * 512 + col] = __float2bfloat16(fmaxf(v, 0.f));
            }
        }
    }
}

// ---------------------------------------------------------------------------
// fp32 GEMM (head only)
// ---------------------------------------------------------------------------
__global__ void __launch_bounds__(256) gemm_nn(
    int M, int N, int K,
    const float* __restrict__ A, int lda,
    const float* __restrict__ B, int ldb,
    float* __restrict__ C, int ldc,
    const float* __restrict__ bias, int flags) {
    __shared__ __align__(16) float As[16][68];
    __shared__ __align__(16) float Bs[16][68];
    int n0 = blockIdx.x * 64, m0 = blockIdx.y * 64;
    int tid = threadIdx.x, tx = tid & 15, ty = tid >> 4;
    int arow = tid >> 2, akg = tid & 3;
    int brow = tid >> 4, bcg = tid & 15;
    float acc[4][4] = {};
    for (int k0 = 0; k0 < K; k0 += 16) {
        float4 av = *(const float4*)(A + (size_t)(m0 + arow) * lda + k0 + 4 * akg);
        float4 bv = *(const float4*)(B + (size_t)(k0 + brow) * ldb + n0 + 4 * bcg);
        __syncthreads();
        As[4 * akg + 0][arow] = av.x; As[4 * akg + 1][arow] = av.y;
        As[4 * akg + 2][arow] = av.z; As[4 * akg + 3][arow] = av.w;
        *(float4*)&Bs[brow][4 * bcg] = bv;
        __syncthreads();
#pragma unroll
        for (int kk = 0; kk < 16; kk++) {
            float4 a = *(const float4*)&As[kk][ty * 4];
            float4 b = *(const float4*)&Bs[kk][tx * 4];
            acc[0][0] += a.x * b.x; acc[0][1] += a.x * b.y;
            acc[0][2] += a.x * b.z; acc[0][3] += a.x * b.w;
            acc[1][0] += a.y * b.x; acc[1][1] += a.y * b.y;
            acc[1][2] += a.y * b.z; acc[1][3] += a.y * b.w;
            acc[2][0] += a.z * b.x; acc[2][1] += a.z * b.y;
            acc[2][2] += a.z * b.z; acc[2][3] += a.z * b.w;
            acc[3][0] += a.w * b.x; acc[3][1] += a.w * b.y;
            acc[3][2] += a.w * b.z; acc[3][3] += a.w * b.w;
        }
    }
#pragma unroll
    for (int mi = 0; mi < 4; mi++) {
        int row = m0 + ty * 4 + mi;
#pragma unroll
        for (int ni = 0; ni < 4; ni++) {
            int col = n0 + tx * 4 + ni;
            float v = acc[mi][ni];
            if (flags & EF_BIAS) v += bias[col];
            if (flags & EF_RELU) v = fmaxf(v, 0.f);
            C[(size_t)row * ldc + col] = v;
        }
    }
}

// ---------------------------------------------------------------------------
// (x += pos?); out = LN(x)*g + b -> bf16.   grid (1024, 2), block 256
// ---------------------------------------------------------------------------
__global__ void addpos_ln(float* __restrict__ x, const float* __restrict__ pos,
                          const float* __restrict__ g, const float* __restrict__ b,
                          bf16* __restrict__ out) {
    size_t rg = (size_t)blockIdx.y * 1024 + blockIdx.x;
    int br = blockIdx.y, t = threadIdx.x;
    float v = x[rg * 256 + t];
    if (pos) {
        v += pos[rg * 256 + t];
        x[rg * 256 + t] = v;
    }
    float mean = blockReduceSum(v) * (1.f / 256.f);
    float d = v - mean;
    float var = blockReduceSum(d * d) * (1.f / 256.f);
    out[rg * 256 + t] = __float2bfloat16(d * rsqrtf(var + 1e-5f) * g[br * 256 + t] + b[br * 256 + t]);
}

__global__ void absdiff(const float* __restrict__ a, const float* __restrict__ b,
                        float* __restrict__ o) {
    int i = blockIdx.x * 256 + threadIdx.x;
    o[i] = fabsf(a[i] - b[i]);
}

__global__ void head2k(const float* __restrict__ hd, const float* __restrict__ W2,
                       const float* __restrict__ b2, float* __restrict__ out) {
    int row = blockIdx.x, t = threadIdx.x;
    float v = hd[row * 128 + t];
    float l0 = v * W2[2 * t], l1 = v * W2[2 * t + 1];
    __shared__ float s0[4], s1[4];
    int lane = t & 31, w = t >> 5;
#pragma unroll
    for (int o = 16; o; o >>= 1) {
        l0 += __shfl_xor_sync(0xffffffffu, l0, o);
        l1 += __shfl_xor_sync(0xffffffffu, l1, o);
    }
    if (lane == 0) { s0[w] = l0; s1[w] = l1; }
    __syncthreads();
    if (t == 0) {
        float a = s0[0] + s0[1] + s0[2] + s0[3] + b2[0];
        float c = s1[0] + s1[1] + s1[2] + s1[3] + b2[1];
        float m = fmaxf(a, c);
        float e0 = expf(a - m), e1 = expf(c - m);
        float inv = 1.f / (e0 + e1);
        out[row * 2 + 0] = e0 * inv;
        out[row * 2 + 1] = e1 * inv;
    }
}

// ---------------------------------------------------------------------------
// Host orchestration: two-stream fork-join, record-before-wait issue order
// ---------------------------------------------------------------------------
extern "C" void kernel_launch(void* const* d_in, const int* in_sizes, int n_in,
                              void* d_out, int out_size) {
    const float* T[2]     = {(const float*)d_in[0], (const float*)d_in[1]};
    const float* Q        = (const float*)d_in[2];
    const float* Am       = (const float*)d_in[3];
    const float* convW_in = (const float*)d_in[4];
    const float* convB_in = (const float*)d_in[5];
    const float* convW    = (const float*)d_in[6];
    const float* convB    = (const float*)d_in[7];
    const float* fc0_b    = (const float*)d_in[9];
    const float* fc_b     = (const float*)d_in[11];
    const float* pos      = (const float*)d_in[12];
    const float* ln1_g    = (const float*)d_in[13];
    const float* ln1_b    = (const float*)d_in[14];
    const float* out_b    = (const float*)d_in[17];
    const float* ln2_g    = (const float*)d_in[18];
    const float* ln2_b    = (const float*)d_in[19];
    const float* ff_b1    = (const float*)d_in[21];
    const float* ff_b2    = (const float*)d_in[23];
    const float* head_W1  = (const float*)d_in[24];
    const float* head_b1  = (const float*)d_in[25];
    const float* head_W2  = (const float*)d_in[26];
    const float* head_b2  = (const float*)d_in[27];
    float* outp = (float*)d_out;

    void* p;
    cudaGetSymbolAddress(&p, g_convb);  bf16* convb = (bf16*)p;
    cudaGetSymbolAddress(&p, g_tb);     bf16* tb = (bf16*)p;
    cudaGetSymbolAddress(&p, g_wb0);    bf16* wb0 = (bf16*)p;
    cudaGetSymbolAddress(&p, g_wbN);    bf16* wbN = (bf16*)p;
    cudaGetSymbolAddress(&p, g_wenc);   bf16* wenc = (bf16*)p;
    cudaGetSymbolAddress(&p, g_amb);    bf16* amb = (bf16*)p;
    cudaGetSymbolAddress(&p, g_catb);   bf16* catb = (bf16*)p;
    cudaGetSymbolAddress(&p, g_hb);     bf16* hb = (bf16*)p;
    cudaGetSymbolAddress(&p, g_qkvb);   bf16* qkvb = (bf16*)p;
    cudaGetSymbolAddress(&p, g_vT);     bf16* vT = (bf16*)p;
    cudaGetSymbolAddress(&p, g_attnob); bf16* attnob = (bf16*)p;
    cudaGetSymbolAddress(&p, g_ff1b);   bf16* ff1b = (bf16*)p;
    cudaGetSymbolAddress(&p, g_x);      float* x = (float*)p;
    cudaGetSymbolAddress(&p, g_dd);     float* dd = (float*)p;
    cudaGetSymbolAddress(&p, g_hd);     float* hd = (float*)p;

    cudaFuncSetAttribute(conv_mma<224>, cudaFuncAttributeMaxDynamicSharedMemorySize, CONV_SMEM);
    cudaFuncSetAttribute(conv_mma<256>, cudaFuncAttributeMaxDynamicSharedMemorySize, CONV_SMEM);
    cudaFuncSetAttribute(fused_attn, cudaFuncAttributeMaxDynamicSharedMemorySize, FA_SMEM);

    // one-time host-side resources (no device memory)
    static cudaStream_t s1 = nullptr;
    static cudaEvent_t evFork, evConv[NSTG], evCt[NSTG];
    if (!s1) {
        cudaStreamCreateWithFlags(&s1, cudaStreamNonBlocking);
        cudaEventCreateWithFlags(&evFork, cudaEventDisableTiming);
        for (int i = 0; i < NSTG; i++) {
            cudaEventCreateWithFlags(&evConv[i], cudaEventDisableTiming);
            cudaEventCreateWithFlags(&evCt[i], cudaEventDisableTiming);
        }
    }

    const long long PP = 4194304;

    // ---- fork ----
    cudaEventRecord(evFork, 0);
    cudaStreamWaitEvent(s1, evFork, 0);

    // ---- conv chain prolog + conv0, conv1 ----
    chw2hwc<<<dim3(512, 7), dim3(32, 8), 0, s1>>>(T[0], tb, 224);
    chw2hwc<<<dim3(512, 7), dim3(32, 8), 0, s1>>>(T[1], tb + 16384ll * 224, 224);
    repack_w<224><<<4032, 256, 0, s1>>>(convW_in, wb0);
    conv_mma<224><<<dim3(64, 2, 2), 256, CONV_SMEM, s1>>>(
        tb, wb0, convB_in, convb, 16384ll * 224, 9ll * 256 * 224, 2 * PP);
    cudaEventRecord(evConv[0], s1);
    repack_w<256><<<23040, 256, 0, s1>>>(convW, wbN);
    conv_mma<256><<<dim3(64, 2, 2), 256, CONV_SMEM, s1>>>(
        convb, wbN, convB, convb + PP, 2 * PP, 9ll * 256 * 256, 2 * PP);
    cudaEventRecord(evConv[1], s1);

    // ---- encoder prolog (main stream) ----
    build_sp<<<1024, 256>>>(Q);
    f32_to_bf16<<<4096, 256>>>(Am, amb);
    wconv_t<<<dim3(48, 8, 12), dim3(32, 8)>>>((const float*)d_in[15], wenc + OFF_QKV, 256, 1536);
    wconv_t<<<dim3(8, 16, 12), dim3(32, 8)>>>((const float*)d_in[16], wenc + OFF_O, 512, 256);
    wconv_t<<<dim3(16, 8, 12), dim3(32, 8)>>>((const float*)d_in[20], wenc + OFF_W1, 256, 512);
    wconv_t<<<dim3(8, 16, 12), dim3(32, 8)>>>((const float*)d_in[22], wenc + OFF_W2, 512, 256);
    wconv_t<<<dim3(8, 15, 2), dim3(32, 8)>>>((const float*)d_in[8], wenc + OFF_FC0, 480, 256);
    wconv_t<<<dim3(8, 16, 10), dim3(32, 8)>>>((const float*)d_in[10], wenc + OFF_FC, 512, 256);
    ct_mean_f32<<<dim3(224, 4), 256>>>(T[0], catb, 256);
    ct_mean_f32<<<dim3(224, 4), 256>>>(T[1], catb + 524288, 256);

    for (int s = 0; s < NSTG; s++) {
        int sbase = s * 2;
        cudaStreamWaitEvent(0, evConv[s], 0);
        ct_nhwc<<<dim3(1024, 2), 256>>>(convb + (s & 1) * PP, 2 * PP, catb, 524288);
        cudaEventRecord(evCt[s], 0);
        if (s + 2 < NSTG) {
            int cw = (s + 1) * 2;
            cudaStreamWaitEvent(s1, evCt[s], 0);
            conv_mma<256><<<dim3(64, 2, 2), 256, CONV_SMEM, s1>>>(
                convb + ((s + 1) & 1) * PP, wbN + (size_t)cw * 9 * 256 * 256,
                convB + cw * 256, convb + (s & 1) * PP, 2 * PP, 9ll * 256 * 256, 2 * PP);
            cudaEventRecord(evConv[s + 2], s1);
        }
        if (s == 0) {
            gemm_bf16<64, 64, 2, 4><<<dim3(4, 16, 2), 256>>>(
                1024, 256, 480, catb, 512, wenc + OFF_FC0, 480, x, 256,
                fc0_b, nullptr, 0, EF_BIAS, 1.f, 1,
                0, 524288, 0, 122880, 0, 262144, 256, 0, nullptr, 0);
        } else {
            int cw = (s - 1) * 2;
            gemm_bf16<64, 64, 2, 4><<<dim3(4, 16, 2), 256>>>(
                1024, 256, 512, catb, 512, wenc + OFF_FC + (size_t)cw * 131072, 512, x, 256,
                fc_b + cw * 256, nullptr, 0, EF_BIAS, 1.f, 1,
                0, 524288, 0, 131072, 0, 262144, 256, 0, nullptr, 0);
        }
        addpos_ln<<<dim3(1024, 2), 256>>>(x, pos + (size_t)sbase * 262144,
                                          ln1_g + sbase * 256, ln1_b + sbase * 256, hb);
        gemm_bf16<128, 128, 2, 4><<<dim3(12, 8, 2), 256>>>(
            1024, 1536, 256, hb, 256, wenc + OFF_QKV + (size_t)sbase * 393216, 256,
            qkvb, 1536, nullptr, nullptr, 0, EF_F16OUT, 1.f, 1,
            0, 262144, 0, 393216, 0, 1572864, 0, 0, nullptr, 0);
        transpose_v<<<dim3(16, 32, 2), dim3(32, 8)>>>(qkvb, vT);
        fused_attn<<<dim3(8, 8, 2), 256, FA_SMEM>>>(qkvb, vT, amb, attnob);
        gemm_bf16<64, 64, 2, 4><<<dim3(4, 16, 2), 256>>>(
            1024, 256, 512, attnob, 512, wenc + OFF_O + (size_t)sbase * 131072, 512, x, 256,
            out_b + sbase * 256, x, 256, EF_BIAS | EF_RES, 1.f, 1,
            0, 524288, 0, 131072, 0, 262144, 256, 262144, nullptr, 0);
        addpos_ln<<<dim3(1024, 2), 256>>>(x, nullptr,
                                          ln2_g + sbase * 256, ln2_b + sbase * 256, hb);
        gemm_bf16<64, 64, 2, 4><<<dim3(8, 16, 2), 256>>>(
            1024, 512, 256, hb, 256, wenc + OFF_W1 + (size_t)sbase * 131072, 256,
            ff1b, 512, ff_b1 + sbase * 512, nullptr, 0,
            EF_BIAS | EF_GELU | EF_F16OUT, 1.f, 1,
            0, 262144, 0, 131072, 0, 524288, 512, 0, nullptr, 0);
        gemm_bf16<64, 64, 2, 4><<<dim3(4, 16, 2), 256>>>(
            1024, 256, 512, ff1b, 512, wenc + OFF_W2 + (size_t)sbase * 131072, 512, x, 256,
            ff_b2 + sbase * 256, x, 256, EF_BIAS | EF_RES | EF_AUX, 1.f, 1,
            0, 524288, 0, 131072, 0, 262144, 256, 262144, catb + 256, 524288);
    }

    // ---- head ----
    absdiff<<<1024, 256>>>(x, x + 262144, dd);
    gemm_nn<<<dim3(2, 16), 256>>>(1024, 128, 256, dd, 256, head_W1, 128,
                                  hd, 128, head_b1, EF_BIAS | EF_RELU);
    head2k<<<1024, 128>>>(hd, head_W2, head_b2, outp);
}

// round 17
// speedup vs baseline: 1.0303x; 1.0001x over previous
#include <cuda_runtime.h>
#include <cuda_bf16.h>
#include <cuda_fp16.h>
#include <cuda_fp8.h>
#include <math.h>

#define SPX   1024
#define HWPX  16384
#define IMW   128
#define NSTG  6

#define EF_BIAS   1
#define EF_RELU   2
#define EF_GELU   4
#define EF_RES    8
#define EF_F16OUT 16
#define EF_AUX    32

typedef __nv_bfloat16 bf16;
typedef __nv_fp8_e4m3 fp8;

// ---------------------------------------------------------------------------
// Scratch
// ---------------------------------------------------------------------------
__device__ fp8   g_convb[4ull * 16384 * 256];    // NHWC fp8 activations [slab*2+br]
__device__ fp8   g_tb[2ull * 16384 * 224];       // NHWC fp8 copies of T1/T2
__device__ fp8   g_wb0[2ull * 9 * 256 * 224];    // stage-0 conv weights (x64, e4m3)
__device__ fp8   g_wbN[10ull * 9 * 256 * 256];   // stage-1..5 conv weights (x64, e4m3)
__device__ bf16  g_wenc[11000832];               // transposed encoder/fc weights
__device__ bf16  g_amb[1024 * 1024];             // bf16 copy of attention bias A
__device__ bf16  g_catb[2ull * 1024 * 512];
__device__ bf16  g_hb[2ull * 1024 * 256];
__device__ bf16  g_qkvb[2ull * 1024 * 1536];
__device__ bf16  g_vT[2ull * 512 * 1024];
__device__ bf16  g_attnob[2ull * 1024 * 512];
__device__ bf16  g_ff1b[2ull * 1024 * 512];
__device__ float g_x[2ull * 1024 * 256];
__device__ float g_dd[1024 * 256];
__device__ float g_hd[1024 * 128];
__device__ int   g_splist[1024 * 64];
__device__ int   g_spcnt[1024];

#define OFF_QKV 0
#define OFF_O   4718592
#define OFF_W1  6291456
#define OFF_W2  7864320
#define OFF_FC0 9437184
#define OFF_FC  9682944

// ---------------------------------------------------------------------------
// cp.async helpers
// ---------------------------------------------------------------------------
#define CPA16(dst, src) \
    asm volatile("cp.async.cg.shared.global [%0], [%1], 16;\n" ::"r"(dst), "l"(src))
#define CPA_COMMIT asm volatile("cp.async.commit_group;\n")
#define CPA_WAIT0  asm volatile("cp.async.wait_group 0;\n")
#define CPA_WAIT1  asm volatile("cp.async.wait_group 1;\n")

// ---------------------------------------------------------------------------
// Block reductions
// ---------------------------------------------------------------------------
__device__ __forceinline__ float blockReduceSum(float v) {
    __shared__ float sh[8];
    int lane = threadIdx.x & 31, w = threadIdx.x >> 5;
#pragma unroll
    for (int o = 16; o; o >>= 1) v += __shfl_xor_sync(0xffffffffu, v, o);
    if (lane == 0) sh[w] = v;
    __syncthreads();
    float r = (threadIdx.x < 8) ? sh[threadIdx.x] : 0.f;
    if (w == 0) {
#pragma unroll
        for (int o = 4; o; o >>= 1) r += __shfl_xor_sync(0xffffffffu, r, o);
        if (lane == 0) sh[0] = r;
    }
    __syncthreads();
    float out = sh[0];
    __syncthreads();
    return out;
}

// ---------------------------------------------------------------------------
// Superpixel list builder
// ---------------------------------------------------------------------------
__global__ void build_sp(const float* __restrict__ Q) {
    int s = blockIdx.x;
    __shared__ int wcnt[8];
    __shared__ int cnt;
    if (threadIdx.x == 0) cnt = 0;
    __syncthreads();
    int lane = threadIdx.x & 31, warp = threadIdx.x >> 5;
    for (int base = 0; base < HWPX; base += 256) {
        int p = base + threadIdx.x;
        bool m = Q[(size_t)p * SPX + s] > 0.5f;
        unsigned bal = __ballot_sync(0xffffffffu, m);
        if (lane == 0) wcnt[warp] = __popc(bal);
        __syncthreads();
        int off = cnt;
        for (int w = 0; w < warp; w++) off += wcnt[w];
        off += __popc(bal & ((1u << lane) - 1u));
        if (m && off < 64) g_splist[s * 64 + off] = p;
        __syncthreads();
        if (threadIdx.x == 0) {
            int t = 0;
            for (int w = 0; w < 8; w++) t += wcnt[w];
            cnt += t;
        }
        __syncthreads();
    }
    if (threadIdx.x == 0) g_spcnt[s] = cnt < 64 ? cnt : 64;
}

// ---------------------------------------------------------------------------
// ct pooling over fp8 NHWC conv activations (MLP-16 fast path)
// ---------------------------------------------------------------------------
__global__ void ct_nhwc(const fp8* __restrict__ img, long long imgz,
                        bf16* __restrict__ out, long long outz) {
    int s = blockIdx.x, c = threadIdx.x;
    img += (size_t)blockIdx.y * imgz;
    out += (size_t)blockIdx.y * outz;
    int cnt = g_spcnt[s];
    const int* lst = &g_splist[s * 64];
    float sum = 0.f;
    if (cnt == 16) {
        int idxs[16];
#pragma unroll
        for (int i = 0; i < 16; i++) idxs[i] = lst[i];
        float v[16];
#pragma unroll
        for (int i = 0; i < 16; i++)
            v[i] = (float)img[(size_t)idxs[i] * 256 + c];
#pragma unroll
        for (int i = 0; i < 16; i++) sum += v[i];
    } else {
        for (int i = 0; i < cnt; i++)
            sum += (float)img[(size_t)lst[i] * 256 + c];
    }
    out[(size_t)s * 512 + c] = __float2bfloat16(fmaxf(sum / (float)cnt, 0.f));
}

__global__ void ct_mean_f32(const float* __restrict__ img, bf16* __restrict__ out,
                            int coloff) {
    int c = blockIdx.x;
    int s = blockIdx.y * 256 + threadIdx.x;
    int cnt = g_spcnt[s];
    const int* lst = &g_splist[s * 64];
    float sum = 0.f;
    for (int i = 0; i < cnt; i++) sum += img[(size_t)c * HWPX + lst[i]];
    out[(size_t)s * 512 + coloff + c] = __float2bfloat16(fmaxf(sum / (float)cnt, 0.f));
}

// NCHW fp32 -> NHWC fp8. grid (512, 7), block (32,8).
__global__ void chw2hwc(const float* __restrict__ in, fp8* __restrict__ out, int C) {
    __shared__ float sm[32][33];
    int p0 = blockIdx.x * 32, c0 = blockIdx.y * 32;
    int tx = threadIdx.x, ty = threadIdx.y;
#pragma unroll
    for (int j = 0; j < 4; j++)
        sm[ty + 8 * j][tx] = in[(size_t)(c0 + ty + 8 * j) * HWPX + p0 + tx];
    __syncthreads();
#pragma unroll
    for (int j = 0; j < 4; j++)
        out[(size_t)(p0 + ty + 8 * j) * C + c0 + tx] = fp8(sm[tx][ty + 8 * j]);
}

__global__ void f32_to_bf16(const float* __restrict__ in, bf16* __restrict__ out) {
    int i = blockIdx.x * 256 + threadIdx.x;
    out[i] = __float2bfloat16(in[i]);
}

// conv weight repack: [z][oc][ic][3][3] f32 -> [z][tap][oc][ic] e4m3 (x64)
template <int CIN>
__global__ void repack_w(const float* __restrict__ W, fp8* __restrict__ out) {
    int idx = blockIdx.x * 256 + threadIdx.x;
    int t = idx / (256 * CIN);
    int z = t / 9, tap = t % 9;
    int rem = idx - t * 256 * CIN;
    int oc = rem / CIN;
    int ic = rem - oc * CIN;
    out[idx] = fp8(W[(size_t)z * 9 * 256 * CIN + ((size_t)oc * CIN + ic) * 9 + tap] * 64.f);
}

// batched transpose+convert: in [Z][K][N] f32 -> out [Z][N][K] bf16
__global__ void wconv_t(const float* __restrict__ in, bf16* __restrict__ out,
                        int K, int N) {
    __shared__ float sm[32][33];
    int n0 = blockIdx.x * 32, k0 = blockIdx.y * 32;
    const float* inz = in + (size_t)blockIdx.z * K * N;
    bf16* outz = out + (size_t)blockIdx.z * K * N;
    int tx = threadIdx.x, ty = threadIdx.y;
#pragma unroll
    for (int j = 0; j < 4; j++)
        sm[ty + 8 * j][tx] = inz[(size_t)(k0 + ty + 8 * j) * N + n0 + tx];
    __syncthreads();
#pragma unroll
    for (int j = 0; j < 4; j++)
        outz[(size_t)(n0 + ty + 8 * j) * K + k0 + tx] = __float2bfloat16(sm[tx][ty + 8 * j]);
}

// transpose V slice of qkv -> vT.  grid (16, 32, 2), block (32, 8).
__global__ void transpose_v(const bf16* __restrict__ qkv, bf16* __restrict__ vT) {
    __shared__ bf16 sm[32][33];
    qkv += (size_t)blockIdx.z * 1024 * 1536;
    vT += (size_t)blockIdx.z * 512 * 1024;
    int c0 = blockIdx.x * 32, m0 = blockIdx.y * 32;
    int tx = threadIdx.x, ty = threadIdx.y;
#pragma unroll
    for (int j = 0; j < 4; j++)
        sm[ty + 8 * j][tx] = qkv[(size_t)(m0 + ty + 8 * j) * 1536 + 1024 + c0 + tx];
    __syncthreads();
#pragma unroll
    for (int j = 0; j < 4; j++)
        vT[(size_t)(c0 + ty + 8 * j) * 1024 + m0 + tx] = sm[tx][ty + 8 * j];
}

// ---------------------------------------------------------------------------
// mma helpers
// ---------------------------------------------------------------------------
__device__ __forceinline__ void mma16816(float* c, const unsigned* a, const unsigned* b) {
    asm volatile(
        "mma.sync.aligned.m16n8k16.row.col.f32.bf16.bf16.f32 "
        "{%0,%1,%2,%3}, {%4,%5,%6,%7}, {%8,%9}, {%0,%1,%2,%3};\n"
        : "+f"(c[0]), "+f"(c[1]), "+f"(c[2]), "+f"(c[3])
        : "r"(a[0]), "r"(a[1]), "r"(a[2]), "r"(a[3]), "r"(b[0]), "r"(b[1]));
}

__device__ __forceinline__ void mma16832fp8(float* c, const unsigned* a, const unsigned* b) {
    asm volatile(
        "mma.sync.aligned.m16n8k32.row.col.f32.e4m3.e4m3.f32 "
        "{%0,%1,%2,%3}, {%4,%5,%6,%7}, {%8,%9}, {%0,%1,%2,%3};\n"
        : "+f"(c[0]), "+f"(c[1]), "+f"(c[2]), "+f"(c[3])
        : "r"(a[0]), "r"(a[1]), "r"(a[2]), "r"(a[3]), "r"(b[0]), "r"(b[1]));
}

__device__ __forceinline__ unsigned packbf(float a, float b) {
    __nv_bfloat162 t = __floats2bfloat162_rn(a, b);
    return *(unsigned*)&t;
}

// ---------------------------------------------------------------------------
// Tensor-core 3x3 SAME conv, NHWC fp8 e4m3, K=32 per mma.
// CTA = 2 rows x 128 oc, occ 1 (proven layout; bytes per chunk unchanged,
// chunk count halved vs bf16).  smem rows keep 48B stride (bf16[24] typed).
// ---------------------------------------------------------------------------
#define CONV_SMEM 161280

template <int CIN>
__global__ void __launch_bounds__(256, 1) conv_mma(
    const fp8* __restrict__ X, const fp8* __restrict__ Wb,
    const float* __restrict__ Bias, fp8* __restrict__ Y,
    long long Xz, long long Wz, long long Yz) {
    extern __shared__ char smem[];
    bf16 (*stageX)[4][132][24] = (bf16(*)[4][132][24])(smem);   // 48B rows: 32B fp8 + pad
    bf16 (*Wt)[9][128][24]     = (bf16(*)[9][128][24])(smem + 50688);
    unsigned char* stageO8     = (unsigned char*)smem;          // [256][144]

    int y0 = blockIdx.x * 2;
    int ochalf = blockIdx.y;
    X += (size_t)blockIdx.z * Xz;
    Wb += (size_t)blockIdx.z * Wz;
    Bias += (size_t)blockIdx.z * 256;
    Y += (size_t)blockIdx.z * Yz;

    int tid = threadIdx.x;
    int lane = tid & 31, wid = tid >> 5;
    int g = lane >> 2, q = lane & 3;
    int mw = wid & 3, nw = wid >> 2;
    int mrow = mw >> 1, mx0 = (mw & 1) * 64;

    const int CH = CIN / 32;
    float acc[4][8][4] = {};

    auto load_chunk = [&](int buf, int ch) {
        int ic0 = ch * 32;
        for (int idx = tid; idx < 1056; idx += 256) {
            int r = idx / 264, rem = idx % 264;
            int pxi = rem >> 1, half = rem & 1;
            int gy = y0 + r - 1, gx = pxi - 1;
            bf16* dst = &stageX[buf][r][pxi][half * 8];
            if (gy >= 0 && gy < 128 && gx >= 0 && gx < 128) {
                const fp8* src = X + ((size_t)gy * IMW + gx) * CIN + ic0 + half * 16;
                CPA16((unsigned)__cvta_generic_to_shared(dst), src);
            } else {
                *(uint4*)dst = make_uint4(0u, 0u, 0u, 0u);
            }
        }
        for (int idx = tid; idx < 2304; idx += 256) {
            int tap = idx / 256, rem = idx % 256;
            int oc = rem >> 1, half = rem & 1;
            bf16* dst = &Wt[buf][tap][oc][half * 8];
            const fp8* src = Wb + ((size_t)tap * 256 + ochalf * 128 + oc) * CIN + ic0 + half * 16;
            CPA16((unsigned)__cvta_generic_to_shared(dst), src);
        }
        CPA_COMMIT;
    };

    load_chunk(0, 0);
    int buf = 0;
    for (int ch = 0; ch < CH; ch++) {
        CPA_WAIT0;
        __syncthreads();
        if (ch + 1 < CH) load_chunk(buf ^ 1, ch + 1);
#pragma unroll
        for (int tap = 0; tap < 9; tap++) {
            int ky = tap / 3, kx = tap % 3;
            unsigned bfr[8][2];
#pragma unroll
            for (int nt = 0; nt < 8; nt++) {
                int oc = nw * 64 + nt * 8 + g;
                bfr[nt][0] = *(const unsigned*)&Wt[buf][tap][oc][q * 2];       // byte q*4
                bfr[nt][1] = *(const unsigned*)&Wt[buf][tap][oc][q * 2 + 8];   // byte 16+q*4
            }
#pragma unroll
            for (int mt = 0; mt < 4; mt++) {
                int p0 = mx0 + mt * 16 + kx;
                unsigned af[4];
                af[0] = *(const unsigned*)&stageX[buf][mrow + ky][p0 + g][q * 2];
                af[1] = *(const unsigned*)&stageX[buf][mrow + ky][p0 + g + 8][q * 2];
                af[2] = *(const unsigned*)&stageX[buf][mrow + ky][p0 + g][q * 2 + 8];
                af[3] = *(const unsigned*)&stageX[buf][mrow + ky][p0 + g + 8][q * 2 + 8];
#pragma unroll
                for (int nt = 0; nt < 8; nt++) mma16832fp8(acc[mt][nt], af, bfr[nt]);
            }
        }
        buf ^= 1;
    }

    // epilogue: descale (weights were x64), bias, store e4m3 NHWC
    const float INV64 = 1.f / 64.f;
    __syncthreads();
#pragma unroll
    for (int mt = 0; mt < 4; mt++) {
#pragma unroll
        for (int nt = 0; nt < 8; nt++) {
            int m = mrow * 128 + mx0 + mt * 16 + g;
            int n = nw * 64 + nt * 8 + q * 2;
            float b0 = Bias[ochalf * 128 + n];
            float b1 = Bias[ochalf * 128 + n + 1];
            stageO8[m * 144 + n]           = fp8(acc[mt][nt][0] * INV64 + b0).__x;
            stageO8[m * 144 + n + 1]       = fp8(acc[mt][nt][1] * INV64 + b1).__x;
            stageO8[(m + 8) * 144 + n]     = fp8(acc[mt][nt][2] * INV64 + b0).__x;
            stageO8[(m + 8) * 144 + n + 1] = fp8(acc[mt][nt][3] * INV64 + b1).__x;
        }
    }
    __syncthreads();
    for (int idx = tid; idx < 2048; idx += 256) {
        int px = idx >> 3, v = idx & 7;
        uint4 val = *(const uint4*)&stageO8[px * 144 + v * 16];
        *(uint4*)((unsigned char*)Y + ((size_t)(y0 + (px >> 7)) * IMW + (px & 127)) * 256
                  + ochalf * 128 + v * 16) = val;
    }
}

// ---------------------------------------------------------------------------
// Fused flash attention; bf16 A bias; probs via ex2.approx.f16x2
// ---------------------------------------------------------------------------
#define FA_SMEM 159744
#define FA_KS   18432
#define FA_VT   55296
#define FA_AS   90112
#define L2E     1.44269504088896f

__global__ void __launch_bounds__(256, 1) fused_attn(
    const bf16* __restrict__ qkv, const bf16* __restrict__ vT,
    const bf16* __restrict__ Amb, bf16* __restrict__ outp) {
    extern __shared__ char smem[];
    bf16 (*Qs)[72]        = (bf16(*)[72])(smem);
    bf16 (*Ks)[128][72]   = (bf16(*)[128][72])(smem + FA_KS);
    bf16 (*VTs)[64][136]  = (bf16(*)[64][136])(smem + FA_VT);
    bf16 (*As)[128][136]  = (bf16(*)[128][136])(smem + FA_AS);

    int rb = blockIdx.x, h = blockIdx.y, br = blockIdx.z;
    qkv += (size_t)br * 1024 * 1536;
    vT += (size_t)br * 512 * 1024;
    outp += (size_t)br * 1024 * 512;

    int tid = threadIdx.x;
    int lane = tid & 31, wid = tid >> 5;
    int g = lane >> 2, q = lane & 3;
    int qrow = wid * 16;

    auto load_j = [&](int buf, int j) {
        int kbase = j * 128;
        for (int idx = tid; idx < 1024; idx += 256) {
            int r = idx >> 3, c = idx & 7;
            CPA16((unsigned)__cvta_generic_to_shared(&Ks[buf][r][c * 8]),
                  qkv + (size_t)(kbase + r) * 1536 + 512 + h * 64 + c * 8);
        }
        for (int idx = tid; idx < 1024; idx += 256) {
            int r = idx >> 4, c = idx & 15;
            CPA16((unsigned)__cvta_generic_to_shared(&VTs[buf][r][c * 8]),
                  vT + (size_t)(h * 64 + r) * 1024 + kbase + c * 8);
        }
        for (int idx = tid; idx < 2048; idx += 256) {
            int r = idx >> 4, c = idx & 15;
            CPA16((unsigned)__cvta_generic_to_shared(&As[buf][r][c * 8]),
                  Amb + (size_t)(rb * 128 + r) * 1024 + kbase + c * 8);
        }
        CPA_COMMIT;
    };

    for (int idx = tid; idx < 1024; idx += 256) {
        int r = idx >> 3, c = idx & 7;
        CPA16((unsigned)__cvta_generic_to_shared(&Qs[r][c * 8]),
              qkv + (size_t)(rb * 128 + r) * 1536 + h * 64 + c * 8);
    }
    load_j(0, 0);

    float m0 = -1e30f, m1 = -1e30f, l0 = 0.f, l1 = 0.f;
    float acc_o[8][4] = {};

    for (int j = 0; j < 8; j++) {
        int buf = j & 1;
        if (j < 7) { load_j(buf ^ 1, j + 1); CPA_WAIT1; }
        else       { CPA_WAIT0; }
        __syncthreads();

        float s[16][4] = {};
#pragma unroll
        for (int ks = 0; ks < 4; ks++) {
            unsigned aq[4];
            aq[0] = *(const unsigned*)&Qs[qrow + g][ks * 16 + q * 2];
            aq[1] = *(const unsigned*)&Qs[qrow + g + 8][ks * 16 + q * 2];
            aq[2] = *(const unsigned*)&Qs[qrow + g][ks * 16 + q * 2 + 8];
            aq[3] = *(const unsigned*)&Qs[qrow + g + 8][ks * 16 + q * 2 + 8];
#pragma unroll
            for (int nt = 0; nt < 16; nt++) {
                unsigned bk[2];
                bk[0] = *(const unsigned*)&Ks[buf][nt * 8 + g][ks * 16 + q * 2];
                bk[1] = *(const unsigned*)&Ks[buf][nt * 8 + g][ks * 16 + q * 2 + 8];
                mma16816(s[nt], aq, bk);
            }
        }
#pragma unroll
        for (int nt = 0; nt < 16; nt++) {
            int col = nt * 8 + q * 2;
            s[nt][0] = s[nt][0] * 0.125f + __bfloat162float(As[buf][qrow + g][col]);
            s[nt][1] = s[nt][1] * 0.125f + __bfloat162float(As[buf][qrow + g][col + 1]);
            s[nt][2] = s[nt][2] * 0.125f + __bfloat162float(As[buf][qrow + g + 8][col]);
            s[nt][3] = s[nt][3] * 0.125f + __bfloat162float(As[buf][qrow + g + 8][col + 1]);
        }
        float mx0 = -1e30f, mx1 = -1e30f;
#pragma unroll
        for (int nt = 0; nt < 16; nt++) {
            mx0 = fmaxf(mx0, fmaxf(s[nt][0], s[nt][1]));
            mx1 = fmaxf(mx1, fmaxf(s[nt][2], s[nt][3]));
        }
#pragma unroll
        for (int o = 1; o <= 2; o <<= 1) {
            mx0 = fmaxf(mx0, __shfl_xor_sync(0xffffffffu, mx0, o));
            mx1 = fmaxf(mx1, __shfl_xor_sync(0xffffffffu, mx1, o));
        }
        float m0n = fmaxf(m0, mx0), m1n = fmaxf(m1, mx1);
        float c0 = exp2f((m0 - m0n) * L2E), c1 = exp2f((m1 - m1n) * L2E);
        float sum0 = 0.f, sum1 = 0.f;
        unsigned p[16][2];
#pragma unroll
        for (int nt = 0; nt < 16; nt++) {
            __half2 e01 = h2exp2(__floats2half2_rn((s[nt][0] - m0n) * L2E,
                                                   (s[nt][1] - m0n) * L2E));
            __half2 e23 = h2exp2(__floats2half2_rn((s[nt][2] - m1n) * L2E,
                                                   (s[nt][3] - m1n) * L2E));
            float2 f01 = __half22float2(e01);
            float2 f23 = __half22float2(e23);
            sum0 += f01.x + f01.y;
            sum1 += f23.x + f23.y;
            p[nt][0] = packbf(f01.x, f01.y);
            p[nt][1] = packbf(f23.x, f23.y);
        }
#pragma unroll
        for (int o = 1; o <= 2; o <<= 1) {
            sum0 += __shfl_xor_sync(0xffffffffu, sum0, o);
            sum1 += __shfl_xor_sync(0xffffffffu, sum1, o);
        }
        l0 = l0 * c0 + sum0;
        l1 = l1 * c1 + sum1;
        m0 = m0n; m1 = m1n;
#pragma unroll
        for (int nto = 0; nto < 8; nto++) {
            acc_o[nto][0] *= c0; acc_o[nto][1] *= c0;
            acc_o[nto][2] *= c1; acc_o[nto][3] *= c1;
        }
#pragma unroll
        for (int ks = 0; ks < 8; ks++) {
            unsigned ap[4] = {p[2 * ks][0], p[2 * ks][1], p[2 * ks + 1][0], p[2 * ks + 1][1]};
#pragma unroll
            for (int nto = 0; nto < 8; nto++) {
                unsigned bv[2];
                bv[0] = *(const unsigned*)&VTs[buf][nto * 8 + g][ks * 16 + q * 2];
                bv[1] = *(const unsigned*)&VTs[buf][nto * 8 + g][ks * 16 + q * 2 + 8];
                mma16816(acc_o[nto], ap, bv);
            }
        }
        __syncthreads();
    }

    float i0 = 1.f / l0, i1 = 1.f / l1;
    int row0 = rb * 128 + qrow + g, row1 = row0 + 8;
#pragma unroll
    for (int nto = 0; nto < 8; nto++) {
        int col = h * 64 + nto * 8 + q * 2;
        *(unsigned*)(outp + (size_t)row0 * 512 + col) = packbf(acc_o[nto][0] * i0, acc_o[nto][1] * i0);
        *(unsigned*)(outp + (size_t)row1 * 512 + col) = packbf(acc_o[nto][2] * i1, acc_o[nto][3] * i1);
    }
}

// ---------------------------------------------------------------------------
// Generic bf16 GEMM with 2-level z batching + optional aux relu-bf16 output
// ---------------------------------------------------------------------------
template <int BM, int BN, int WRM, int WRN>
__global__ void __launch_bounds__(256) gemm_bf16(
    int M, int N, int K,
    const bf16* __restrict__ A, int lda,
    const bf16* __restrict__ B, int ldb,
    void* __restrict__ Cv, int ldc,
    const float* __restrict__ bias,
    const float* __restrict__ res, int ldr,
    int flags, float alpha, int zmod,
    long long Az1, long long Az2, long long Bz1, long long Bz2,
    long long Cz1, long long Cz2, long long bz2, long long Rz2,
    bf16* __restrict__ aux, long long auxz2) {
    const int WM = BM / WRM, WN = BN / WRN;
    const int MT = WM / 16, NT = WN / 8;
    __shared__ __align__(16) bf16 As[BM][40];
    __shared__ __align__(16) bf16 Bs[BN][40];

    long long z = blockIdx.z;
    long long z1 = z % zmod, z2 = z / zmod;
    A += z1 * Az1 + z2 * Az2;
    B += z1 * Bz1 + z2 * Bz2;
    long long coff = z1 * Cz1 + z2 * Cz2;
    if (bias) bias += z2 * bz2;
    if (res) res += z2 * Rz2;
    if (aux) aux += z2 * auxz2;

    int m0 = blockIdx.y * BM, n0 = blockIdx.x * BN;
    int tid = threadIdx.x, lane = tid & 31, wid = tid >> 5;
    int g = lane >> 2, q = lane & 3;
    int wm0 = (wid % WRM) * WM, wn0 = (wid / WRM) * WN;

    float acc[MT][NT][4] = {};

    for (int k0 = 0; k0 < K; k0 += 32) {
        __syncthreads();
#pragma unroll
        for (int r = 0; r < BM * 4 / 256; r++) {
            int idx = tid + r * 256;
            int row = idx >> 2, quad = idx & 3;
            uint4 v = *(const uint4*)(A + (size_t)(m0 + row) * lda + k0 + quad * 8);
            *(uint4*)&As[row][quad * 8] = v;
        }
#pragma unroll
        for (int r = 0; r < BN * 4 / 256; r++) {
            int idx = tid + r * 256;
            int row = idx >> 2, quad = idx & 3;
            uint4 v = *(const uint4*)(B + (size_t)(n0 + row) * ldb + k0 + quad * 8);
            *(uint4*)&Bs[row][quad * 8] = v;
        }
        __syncthreads();
#pragma unroll
        for (int kk = 0; kk < 2; kk++) {
            unsigned af[MT][4], bfr[NT][2];
#pragma unroll
            for (int mt = 0; mt < MT; mt++) {
                int row = wm0 + mt * 16 + g;
                af[mt][0] = *(const unsigned*)&As[row][kk * 16 + q * 2];
                af[mt][1] = *(const unsigned*)&As[row + 8][kk * 16 + q * 2];
                af[mt][2] = *(const unsigned*)&As[row][kk * 16 + q * 2 + 8];
                af[mt][3] = *(const unsigned*)&As[row + 8][kk * 16 + q * 2 + 8];
            }
#pragma unroll
            for (int nt = 0; nt < NT; nt++) {
                int col = wn0 + nt * 8 + g;
                bfr[nt][0] = *(const unsigned*)&Bs[col][kk * 16 + q * 2];
                bfr[nt][1] = *(const unsigned*)&Bs[col][kk * 16 + q * 2 + 8];
            }
#pragma unroll
            for (int mt = 0; mt < MT; mt++)
#pragma unroll
                for (int nt = 0; nt < NT; nt++) mma16816(acc[mt][nt], af[mt], bfr[nt]);
        }
    }

    float* Cf = (float*)Cv + coff;
    bf16* Ch = (bf16*)Cv + coff;
#pragma unroll
    for (int mt = 0; mt < MT; mt++) {
#pragma unroll
        for (int nt = 0; nt < NT; nt++) {
#pragma unroll
            for (int e = 0; e < 4; e++) {
                int row = m0 + wm0 + mt * 16 + g + (e >> 1) * 8;
                int col = n0 + wn0 + nt * 8 + q * 2 + (e & 1);
                float v = acc[mt][nt][e] * alpha;
                if (flags & EF_RES)  v += res[(size_t)row * ldr + col];
                if (flags & EF_BIAS) v += bias[col];
                if (flags & EF_RELU) v = fmaxf(v, 0.f);
                if (flags & EF_GELU) v = 0.5f * v * (1.f + erff(v * 0.70710678118654752f));
                if (flags & EF_F16OUT) Ch[(size_t)row * ldc + col] = __float2bfloat16(v);
                else                   Cf[(size_t)row * ldc + col] = v;
                if (flags & EF_AUX)
                    aux[(size_t)row * 512 + col] = __float2bfloat16(fmaxf(v, 0.f));
            }
        }
    }
}

// ---------------------------------------------------------------------------
// fp32 GEMM (head only)
// ---------------------------------------------------------------------------
__global__ void __launch_bounds__(256) gemm_nn(
    int M, int N, int K,
    const float* __restrict__ A, int lda,
    const float* __restrict__ B, int ldb,
    float* __restrict__ C, int ldc,
    const float* __restrict__ bias, int flags) {
    __shared__ __align__(16) float As[16][68];
    __shared__ __align__(16) float Bs[16][68];
    int n0 = blockIdx.x * 64, m0 = blockIdx.y * 64;
    int tid = threadIdx.x, tx = tid & 15, ty = tid >> 4;
    int arow = tid >> 2, akg = tid & 3;
    int brow = tid >> 4, bcg = tid & 15;
    float acc[4][4] = {};
    for (int k0 = 0; k0 < K; k0 += 16) {
        float4 av = *(const float4*)(A + (size_t)(m0 + arow) * lda + k0 + 4 * akg);
        float4 bv = *(const float4*)(B + (size_t)(k0 + brow) * ldb + n0 + 4 * bcg);
        __syncthreads();
        As[4 * akg + 0][arow] = av.x; As[4 * akg + 1][arow] = av.y;
        As[4 * akg + 2][arow] = av.z; As[4 * akg + 3][arow] = av.w;
        *(float4*)&Bs[brow][4 * bcg] = bv;
        __syncthreads();
#pragma unroll
        for (int kk = 0; kk < 16; kk++) {
            float4 a = *(const float4*)&As[kk][ty * 4];
            float4 b = *(const float4*)&Bs[kk][tx * 4];
            acc[0][0] += a.x * b.x; acc[0][1] += a.x * b.y;
            acc[0][2] += a.x * b.z; acc[0][3] += a.x * b.w;
            acc[1][0] += a.y * b.x; acc[1][1] += a.y * b.y;
            acc[1][2] += a.y * b.z; acc[1][3] += a.y * b.w;
            acc[2][0] += a.z * b.x; acc[2][1] += a.z * b.y;
            acc[2][2] += a.z * b.z; acc[2][3] += a.z * b.w;
            acc[3][0] += a.w * b.x; acc[3][1] += a.w * b.y;
            acc[3][2] += a.w * b.z; acc[3][3] += a.w * b.w;
        }
    }
#pragma unroll
    for (int mi = 0; mi < 4; mi++) {
        int row = m0 + ty * 4 + mi;
#pragma unroll
        for (int ni = 0; ni < 4; ni++) {
            int col = n0 + tx * 4 + ni;
            float v = acc[mi][ni];
            if (flags & EF_BIAS) v += bias[col];
            if (flags & EF_RELU) v = fmaxf(v, 0.f);
            C[(size_t)row * ldc + col] = v;
        }
    }
}

// ---------------------------------------------------------------------------
// (x += pos?); out = LN(x)*g + b -> bf16.   grid (1024, 2), block 256
// ---------------------------------------------------------------------------
__global__ void addpos_ln(float* __restrict__ x, const float* __restrict__ pos,
                          const float* __restrict__ g, const float* __restrict__ b,
                          bf16* __restrict__ out) {
    size_t rg = (size_t)blockIdx.y * 1024 + blockIdx.x;
    int br = blockIdx.y, t = threadIdx.x;
    float v = x[rg * 256 + t];
    if (pos) {
        v += pos[rg * 256 + t];
        x[rg * 256 + t] = v;
    }
    float mean = blockReduceSum(v) * (1.f / 256.f);
    float d = v - mean;
    float var = blockReduceSum(d * d) * (1.f / 256.f);
    out[rg * 256 + t] = __float2bfloat16(d * rsqrtf(var + 1e-5f) * g[br * 256 + t] + b[br * 256 + t]);
}

__global__ void absdiff(const float* __restrict__ a, const float* __restrict__ b,
                        float* __restrict__ o) {
    int i = blockIdx.x * 256 + threadIdx.x;
    o[i] = fabsf(a[i] - b[i]);
}

__global__ void head2k(const float* __restrict__ hd, const float* __restrict__ W2,
                       const float* __restrict__ b2, float* __restrict__ out) {
    int row = blockIdx.x, t = threadIdx.x;
    float v = hd[row * 128 + t];
    float l0 = v * W2[2 * t], l1 = v * W2[2 * t + 1];
    __shared__ float s0[4], s1[4];
    int lane = t & 31, w = t >> 5;
#pragma unroll
    for (int o = 16; o; o >>= 1) {
        l0 += __shfl_xor_sync(0xffffffffu, l0, o);
        l1 += __shfl_xor_sync(0xffffffffu, l1, o);
    }
    if (lane == 0) { s0[w] = l0; s1[w] = l1; }
    __syncthreads();
    if (t == 0) {
        float a = s0[0] + s0[1] + s0[2] + s0[3] + b2[0];
        float c = s1[0] + s1[1] + s1[2] + s1[3] + b2[1];
        float m = fmaxf(a, c);
        float e0 = expf(a - m), e1 = expf(c - m);
        float inv = 1.f / (e0 + e1);
        out[row * 2 + 0] = e0 * inv;
        out[row * 2 + 1] = e1 * inv;
    }
}

// ---------------------------------------------------------------------------
// Host orchestration: two-stream fork-join, record-before-wait issue order
// ---------------------------------------------------------------------------
extern "C" void kernel_launch(void* const* d_in, const int* in_sizes, int n_in,
                              void* d_out, int out_size) {
    const float* T[2]     = {(const float*)d_in[0], (const float*)d_in[1]};
    const float* Q        = (const float*)d_in[2];
    const float* Am       = (const float*)d_in[3];
    const float* convW_in = (const float*)d_in[4];
    const float* convB_in = (const float*)d_in[5];
    const float* convW    = (const float*)d_in[6];
    const float* convB    = (const float*)d_in[7];
    const float* fc0_b    = (const float*)d_in[9];
    const float* fc_b     = (const float*)d_in[11];
    const float* pos      = (const float*)d_in[12];
    const float* ln1_g    = (const float*)d_in[13];
    const float* ln1_b    = (const float*)d_in[14];
    const float* out_b    = (const float*)d_in[17];
    const float* ln2_g    = (const float*)d_in[18];
    const float* ln2_b    = (const float*)d_in[19];
    const float* ff_b1    = (const float*)d_in[21];
    const float* ff_b2    = (const float*)d_in[23];
    const float* head_W1  = (const float*)d_in[24];
    const float* head_b1  = (const float*)d_in[25];
    const float* head_W2  = (const float*)d_in[26];
    const float* head_b2  = (const float*)d_in[27];
    float* outp = (float*)d_out;

    void* p;
    cudaGetSymbolAddress(&p, g_convb);  fp8* convb = (fp8*)p;
    cudaGetSymbolAddress(&p, g_tb);     fp8* tb = (fp8*)p;
    cudaGetSymbolAddress(&p, g_wb0);    fp8* wb0 = (fp8*)p;
    cudaGetSymbolAddress(&p, g_wbN);    fp8* wbN = (fp8*)p;
    cudaGetSymbolAddress(&p, g_wenc);   bf16* wenc = (bf16*)p;
    cudaGetSymbolAddress(&p, g_amb);    bf16* amb = (bf16*)p;
    cudaGetSymbolAddress(&p, g_catb);   bf16* catb = (bf16*)p;
    cudaGetSymbolAddress(&p, g_hb);     bf16* hb = (bf16*)p;
    cudaGetSymbolAddress(&p, g_qkvb);   bf16* qkvb = (bf16*)p;
    cudaGetSymbolAddress(&p, g_vT);     bf16* vT = (bf16*)p;
    cudaGetSymbolAddress(&p, g_attnob); bf16* attnob = (bf16*)p;
    cudaGetSymbolAddress(&p, g_ff1b);   bf16* ff1b = (bf16*)p;
    cudaGetSymbolAddress(&p, g_x);      float* x = (float*)p;
    cudaGetSymbolAddress(&p, g_dd);     float* dd = (float*)p;
    cudaGetSymbolAddress(&p, g_hd);     float* hd = (float*)p;

    cudaFuncSetAttribute(conv_mma<224>, cudaFuncAttributeMaxDynamicSharedMemorySize, CONV_SMEM);
    cudaFuncSetAttribute(conv_mma<256>, cudaFuncAttributeMaxDynamicSharedMemorySize, CONV_SMEM);
    cudaFuncSetAttribute(fused_attn, cudaFuncAttributeMaxDynamicSharedMemorySize, FA_SMEM);

    // one-time host-side resources (no device memory)
    static cudaStream_t s1 = nullptr;
    static cudaEvent_t evFork, evConv[NSTG], evCt[NSTG];
    if (!s1) {
        cudaStreamCreateWithFlags(&s1, cudaStreamNonBlocking);
        cudaEventCreateWithFlags(&evFork, cudaEventDisableTiming);
        for (int i = 0; i < NSTG; i++) {
            cudaEventCreateWithFlags(&evConv[i], cudaEventDisableTiming);
            cudaEventCreateWithFlags(&evCt[i], cudaEventDisableTiming);
        }
    }

    const long long PP = 4194304;   // one fp8 activation slab (16384*256 bytes)

    // ---- fork ----
    cudaEventRecord(evFork, 0);
    cudaStreamWaitEvent(s1, evFork, 0);

    // ---- conv chain prolog + conv0, conv1 ----
    chw2hwc<<<dim3(512, 7), dim3(32, 8), 0, s1>>>(T[0], tb, 224);
    chw2hwc<<<dim3(512, 7), dim3(32, 8), 0, s1>>>(T[1], tb + 16384ll * 224, 224);
    repack_w<224><<<4032, 256, 0, s1>>>(convW_in, wb0);
    conv_mma<224><<<dim3(64, 2, 2), 256, CONV_SMEM, s1>>>(
        tb, wb0, convB_in, convb, 16384ll * 224, 9ll * 256 * 224, 2 * PP);
    cudaEventRecord(evConv[0], s1);
    repack_w<256><<<23040, 256, 0, s1>>>(convW, wbN);
    conv_mma<256><<<dim3(64, 2, 2), 256, CONV_SMEM, s1>>>(
        convb, wbN, convB, convb + PP, 2 * PP, 9ll * 256 * 256, 2 * PP);
    cudaEventRecord(evConv[1], s1);

    // ---- encoder prolog (main stream) ----
    build_sp<<<1024, 256>>>(Q);
    f32_to_bf16<<<4096, 256>>>(Am, amb);
    wconv_t<<<dim3(48, 8, 12), dim3(32, 8)>>>((const float*)d_in[15], wenc + OFF_QKV, 256, 1536);
    wconv_t<<<dim3(8, 16, 12), dim3(32, 8)>>>((const float*)d_in[16], wenc + OFF_O, 512, 256);
    wconv_t<<<dim3(16, 8, 12), dim3(32, 8)>>>((const float*)d_in[20], wenc + OFF_W1, 256, 512);
    wconv_t<<<dim3(8, 16, 12), dim3(32, 8)>>>((const float*)d_in[22], wenc + OFF_W2, 512, 256);
    wconv_t<<<dim3(8, 15, 2), dim3(32, 8)>>>((const float*)d_in[8], wenc + OFF_FC0, 480, 256);
    wconv_t<<<dim3(8, 16, 10), dim3(32, 8)>>>((const float*)d_in[10], wenc + OFF_FC, 512, 256);
    ct_mean_f32<<<dim3(224, 4), 256>>>(T[0], catb, 256);
    ct_mean_f32<<<dim3(224, 4), 256>>>(T[1], catb + 524288, 256);

    for (int s = 0; s < NSTG; s++) {
        int sbase = s * 2;
        cudaStreamWaitEvent(0, evConv[s], 0);
        ct_nhwc<<<dim3(1024, 2), 256>>>(convb + (s & 1) * PP, 2 * PP, catb, 524288);
        cudaEventRecord(evCt[s], 0);
        if (s + 2 < NSTG) {
            int cw = (s + 1) * 2;
            cudaStreamWaitEvent(s1, evCt[s], 0);
            conv_mma<256><<<dim3(64, 2, 2), 256, CONV_SMEM, s1>>>(
                convb + ((s + 1) & 1) * PP, wbN + (size_t)cw * 9 * 256 * 256,
                convB + cw * 256, convb + (s & 1) * PP, 2 * PP, 9ll * 256 * 256, 2 * PP);
            cudaEventRecord(evConv[s + 2], s1);
        }
        if (s == 0) {
            gemm_bf16<64, 64, 2, 4><<<dim3(4, 16, 2), 256>>>(
                1024, 256, 480, catb, 512, wenc + OFF_FC0, 480, x, 256,
                fc0_b, nullptr, 0, EF_BIAS, 1.f, 1,
                0, 524288, 0, 122880, 0, 262144, 256, 0, nullptr, 0);
        } else {
            int cw = (s - 1) * 2;
            gemm_bf16<64, 64, 2, 4><<<dim3(4, 16, 2), 256>>>(
                1024, 256, 512, catb, 512, wenc + OFF_FC + (size_t)cw * 131072, 512, x, 256,
                fc_b + cw * 256, nullptr, 0, EF_BIAS, 1.f, 1,
                0, 524288, 0, 131072, 0, 262144, 256, 0, nullptr, 0);
        }
        addpos_ln<<<dim3(1024, 2), 256>>>(x, pos + (size_t)sbase * 262144,
                                          ln1_g + sbase * 256, ln1_b + sbase * 256, hb);
        gemm_bf16<128, 128, 2, 4><<<dim3(12, 8, 2), 256>>>(
            1024, 1536, 256, hb, 256, wenc + OFF_QKV + (size_t)sbase * 393216, 256,
            qkvb, 1536, nullptr, nullptr, 0, EF_F16OUT, 1.f, 1,
            0, 262144, 0, 393216, 0, 1572864, 0, 0, nullptr, 0);
        transpose_v<<<dim3(16, 32, 2), dim3(32, 8)>>>(qkvb, vT);
        fused_attn<<<dim3(8, 8, 2), 256, FA_SMEM>>>(qkvb, vT, amb, attnob);
        gemm_bf16<64, 64, 2, 4><<<dim3(4, 16, 2), 256>>>(
            1024, 256, 512, attnob, 512, wenc + OFF_O + (size_t)sbase * 131072, 512, x, 256,
            out_b + sbase * 256, x, 256, EF_BIAS | EF_RES, 1.f, 1,
            0, 524288, 0, 131072, 0, 262144, 256, 262144, nullptr, 0);
        addpos_ln<<<dim3(1024, 2), 256>>>(x, nullptr,
                                          ln2_g + sbase * 256, ln2_b + sbase * 256, hb);
        gemm_bf16<64, 64, 2, 4><<<dim3(8, 16, 2), 256>>>(
            1024, 512, 256, hb, 256, wenc + OFF_W1 + (size_t)sbase * 131072, 256,
            ff1b, 512, ff_b1 + sbase * 512, nullptr, 0,
            EF_BIAS | EF_GELU | EF_F16OUT, 1.f, 1,
            0, 262144, 0, 131072, 0, 524288, 512, 0, nullptr, 0);
        gemm_bf16<64, 64, 2, 4><<<dim3(4, 16, 2), 256>>>(
            1024, 256, 512, ff1b, 512, wenc + OFF_W2 + (size_t)sbase * 131072, 512, x, 256,
            ff_b2 + sbase * 256, x, 256, EF_BIAS | EF_RES | EF_AUX, 1.f, 1,
            0, 524288, 0, 131072, 0, 262144, 256, 262144, catb + 256, 524288);
    }

    // ---- head ----
    absdiff<<<1024, 256>>>(x, x + 262144, dd);
    gemm_nn<<<dim3(2, 16), 256>>>(1024, 128, 256, dd, 256, head_W1, 128,
                                  hd, 128, head_b1, EF_BIAS | EF_RELU);
    head2k<<<1024, 128>>>(hd, head_W2, head_b2, outp);
}